// round 1
// baseline (speedup 1.0000x reference)
#include <cuda_runtime.h>
#include <math.h>

#define NN 8
#define C 128
#define CWCH 64
#define H 96
#define W 96
#define HW (H*W)
#define CIN 192
#define NB 6
#define TEM 6

// Scratch (allocation-free rule: __device__ globals)
__device__ float g_hmid[(size_t)NN*C*HW];            // 37.7 MB
__device__ float g_bases[(size_t)NN*NB*9*HW];        // 15.9 MB  layout [n][m][l][hw]
__device__ float g_bout[(size_t)NN*C*NB*HW];         // 226 MB   layout [n][c*6+m][hw]

// ---------------------------------------------------------------------------
// Kernel 1: conv1 3x3 (Cin=192 concat(feat,weight) -> 128) + tanh
// tile: 32 wide x 16 high x 32 cout; 256 threads; 2 pixels/thread
// ---------------------------------------------------------------------------
__global__ __launch_bounds__(256) void conv1_kernel(
    const float* __restrict__ feat, const float* __restrict__ wtin,
    const float* __restrict__ w1, const float* __restrict__ b1)
{
    const int tx = threadIdx.x & 31;
    const int ty = threadIdx.x >> 5;        // 0..7
    const int w0 = blockIdx.x * 32;
    const int h0 = blockIdx.y * 16;
    const int n  = blockIdx.z >> 2;
    const int cog = blockIdx.z & 3;

    __shared__ float s_in[18 * 34];
    __shared__ float s_w[32 * 9];

    float acc0[32], acc1[32];
#pragma unroll
    for (int i = 0; i < 32; i++) { acc0[i] = 0.f; acc1[i] = 0.f; }

    for (int ci = 0; ci < CIN; ci++) {
        const float* src = (ci < C) ? (feat + ((size_t)n * C + ci) * HW)
                                    : (wtin + ((size_t)n * CWCH + (ci - C)) * HW);
        for (int idx = threadIdx.x; idx < 18 * 34; idx += 256) {
            int r = idx / 34, cc = idx - r * 34;
            int gh = h0 + r - 1, gw = w0 + cc - 1;
            float v = 0.f;
            if (gh >= 0 && gh < H && gw >= 0 && gw < W) v = src[gh * W + gw];
            s_in[idx] = v;
        }
        for (int idx = threadIdx.x; idx < 288; idx += 256) {
            int co = idx / 9, l = idx - co * 9;
            s_w[idx] = w1[((size_t)(cog * 32 + co) * CIN + ci) * 9 + l];
        }
        __syncthreads();

        float in0[9], in1[9];
#pragma unroll
        for (int i = 0; i < 3; i++)
#pragma unroll
            for (int j = 0; j < 3; j++) {
                in0[i * 3 + j] = s_in[(ty + i) * 34 + tx + j];
                in1[i * 3 + j] = s_in[(ty + 8 + i) * 34 + tx + j];
            }
#pragma unroll
        for (int co = 0; co < 32; co++) {
#pragma unroll
            for (int l = 0; l < 9; l++) {
                float wv = s_w[co * 9 + l];
                acc0[co] = fmaf(in0[l], wv, acc0[co]);
                acc1[co] = fmaf(in1[l], wv, acc1[co]);
            }
        }
        __syncthreads();
    }

#pragma unroll
    for (int co = 0; co < 32; co++) {
        float bb = b1[cog * 32 + co];
        size_t base = ((size_t)n * C + cog * 32 + co) * HW;
        g_hmid[base + (size_t)(h0 + ty) * W + w0 + tx]     = tanhf(acc0[co] + bb);
        g_hmid[base + (size_t)(h0 + ty + 8) * W + w0 + tx] = tanhf(acc1[co] + bb);
    }
}

// ---------------------------------------------------------------------------
// Kernel 2: conv2 1x1 (128 -> 36) + tanh, then bases[m][l] = sum_t b[m,t]*bb[t,l]
// one thread per pixel
// ---------------------------------------------------------------------------
__global__ __launch_bounds__(256) void conv2_bases_kernel(
    const float* __restrict__ w2, const float* __restrict__ b2,
    const float* __restrict__ bb)
{
    __shared__ float s_w2[36 * 128];
    __shared__ float s_b2[36];
    __shared__ float s_bb[54];
    for (int idx = threadIdx.x; idx < 36 * 128; idx += 256) s_w2[idx] = w2[idx];
    if (threadIdx.x < 36) s_b2[threadIdx.x] = b2[threadIdx.x];
    if (threadIdx.x < 54) s_bb[threadIdx.x] = bb[threadIdx.x];
    __syncthreads();

    const int n = blockIdx.y;
    const int p = blockIdx.x * 256 + threadIdx.x;

    float acc[36];
#pragma unroll
    for (int j = 0; j < 36; j++) acc[j] = s_b2[j];

    const float* hm = g_hmid + (size_t)n * C * HW + p;
    for (int c = 0; c < C; c++) {
        float v = hm[(size_t)c * HW];
#pragma unroll
        for (int j = 0; j < 36; j++) acc[j] = fmaf(v, s_w2[j * 128 + c], acc[j]);
    }
#pragma unroll
    for (int j = 0; j < 36; j++) acc[j] = tanhf(acc[j]);

    float* bout = g_bases + (size_t)n * NB * 9 * HW + p;
#pragma unroll
    for (int m = 0; m < NB; m++) {
#pragma unroll
        for (int l = 0; l < 9; l++) {
            float s = 0.f;
#pragma unroll
            for (int t = 0; t < TEM; t++) s = fmaf(acc[m * 6 + t], s_bb[t * 9 + l], s);
            bout[(size_t)(m * 9 + l) * HW] = s;
        }
    }
}

// ---------------------------------------------------------------------------
// Kernel 3: bases_out[n, c*6+m, p] = sum_l bases[n,m,l,p] * patch(feat; c, l, p)
// 16x16 spatial tile; smem feat tile per channel
// ---------------------------------------------------------------------------
__global__ __launch_bounds__(256) void bases_out_kernel(const float* __restrict__ feat)
{
    const int tx = threadIdx.x & 15;
    const int ty = threadIdx.x >> 4;
    const int w0 = blockIdx.x * 16, h0 = blockIdx.y * 16;
    const int n = blockIdx.z;
    __shared__ float s_in[18 * 18];

    const int p = (h0 + ty) * W + (w0 + tx);
    float bas[NB][9];
    const float* bsrc = g_bases + (size_t)n * NB * 9 * HW + p;
#pragma unroll
    for (int m = 0; m < NB; m++)
#pragma unroll
        for (int l = 0; l < 9; l++) bas[m][l] = bsrc[(size_t)(m * 9 + l) * HW];

    float* outp = g_bout + (size_t)n * (C * NB) * HW + p;
    for (int c = 0; c < C; c++) {
        const float* src = feat + ((size_t)n * C + c) * HW;
        __syncthreads();
        for (int idx = threadIdx.x; idx < 18 * 18; idx += 256) {
            int r = idx / 18, cc = idx - r * 18;
            int gh = h0 + r - 1, gw = w0 + cc - 1;
            s_in[idx] = (gh >= 0 && gh < H && gw >= 0 && gw < W) ? src[gh * W + gw] : 0.f;
        }
        __syncthreads();
        float px[9];
#pragma unroll
        for (int i = 0; i < 3; i++)
#pragma unroll
            for (int j = 0; j < 3; j++) px[i * 3 + j] = s_in[(ty + i) * 18 + tx + j];
#pragma unroll
        for (int m = 0; m < NB; m++) {
            float s = 0.f;
#pragma unroll
            for (int l = 0; l < 9; l++) s = fmaf(bas[m][l], px[l], s);
            outp[(size_t)(c * NB + m) * HW] = s;
        }
    }
}

// ---------------------------------------------------------------------------
// Kernel 4: out[n,co,p] = bias[co] + sum_{k<768} coef[co,k] * g_bout[n,k,p]
// block: 512 pixels (2/thread) x 32 couts; coef chunked through smem
// ---------------------------------------------------------------------------
__global__ __launch_bounds__(256) void final_kernel(
    const float* __restrict__ coef, const float* __restrict__ bias,
    float* __restrict__ out)
{
    const int tid = threadIdx.x;
    const int n = blockIdx.z;
    const int cog = blockIdx.y;
    const int p = blockIdx.x * 512 + tid;   // and p+256

    __shared__ float s_c[32 * 32];
    float acc0[32], acc1[32];
#pragma unroll
    for (int i = 0; i < 32; i++) { acc0[i] = 0.f; acc1[i] = 0.f; }

    const float* T = g_bout + (size_t)n * (C * NB) * HW;
    for (int k0 = 0; k0 < C * NB; k0 += 32) {
        __syncthreads();
        for (int idx = tid; idx < 32 * 32; idx += 256) {
            int co = idx >> 5, kk = idx & 31;
            s_c[idx] = coef[(size_t)(cog * 32 + co) * (C * NB) + k0 + kk];
        }
        __syncthreads();
#pragma unroll
        for (int kk = 0; kk < 32; kk++) {
            float v0 = T[(size_t)(k0 + kk) * HW + p];
            float v1 = T[(size_t)(k0 + kk) * HW + p + 256];
#pragma unroll
            for (int co = 0; co < 32; co++) {
                float wv = s_c[co * 32 + kk];
                acc0[co] = fmaf(v0, wv, acc0[co]);
                acc1[co] = fmaf(v1, wv, acc1[co]);
            }
        }
    }
#pragma unroll
    for (int co = 0; co < 32; co++) {
        float bv = bias[cog * 32 + co];
        size_t base = ((size_t)n * C + cog * 32 + co) * HW;
        out[base + p]       = acc0[co] + bv;
        out[base + p + 256] = acc1[co] + bv;
    }
}

// ---------------------------------------------------------------------------
extern "C" void kernel_launch(void* const* d_in, const int* in_sizes, int n_in,
                              void* d_out, int out_size)
{
    const float* feat  = (const float*)d_in[0];
    const float* wtin  = (const float*)d_in[1];
    const float* w1    = (const float*)d_in[2];
    const float* b1    = (const float*)d_in[3];
    const float* w2    = (const float*)d_in[4];
    const float* b2    = (const float*)d_in[5];
    const float* bb    = (const float*)d_in[6];
    const float* coef  = (const float*)d_in[7];
    const float* bias  = (const float*)d_in[8];
    float* out = (float*)d_out;

    conv1_kernel<<<dim3(3, 6, NN * 4), 256>>>(feat, wtin, w1, b1);
    conv2_bases_kernel<<<dim3(HW / 256, NN), 256>>>(w2, b2, bb);
    bases_out_kernel<<<dim3(6, 6, NN), 256>>>(feat);
    final_kernel<<<dim3(HW / 512, 4, NN), 256>>>(coef, bias, out);
}

// round 4
// speedup vs baseline: 1.2341x; 1.2341x over previous
#include <cuda_runtime.h>
#include <math.h>

#define NN 8
#define C 128
#define CWCH 64
#define H 96
#define W 96
#define HW (H*W)
#define CIN 192
#define NB 6
#define TEM 6
#define KTOT (C*NB)          // 768

// Scratch (allocation-free rule: __device__ globals)
__device__ float g_hmid[(size_t)NN*C*HW];            // 37.7 MB
__device__ float g_bases[(size_t)NN*NB*9*HW];        // 15.9 MB  layout [n][m*9+l][hw]
__device__ float g_coefT[(size_t)KTOT*C];            // 393 KB   layout [k][co]

// ---------------------------------------------------------------------------
// Kernel 0: transpose coef (co-major -> k-major) for coalesced smem staging
// ---------------------------------------------------------------------------
__global__ __launch_bounds__(256) void coefT_kernel(const float* __restrict__ coef)
{
    int idx = blockIdx.x * 256 + threadIdx.x;        // 98304 total
    int co = idx / KTOT, k = idx - co * KTOT;
    g_coefT[(size_t)k * C + co] = coef[idx];
}

// ---------------------------------------------------------------------------
// Kernel 1: conv1 3x3 (Cin=192 concat(feat,weight) -> 128) + tanh
// ---------------------------------------------------------------------------
__global__ __launch_bounds__(256) void conv1_kernel(
    const float* __restrict__ feat, const float* __restrict__ wtin,
    const float* __restrict__ w1, const float* __restrict__ b1)
{
    const int tx = threadIdx.x & 31;
    const int ty = threadIdx.x >> 5;        // 0..7
    const int w0 = blockIdx.x * 32;
    const int h0 = blockIdx.y * 16;
    const int n  = blockIdx.z >> 2;
    const int cog = blockIdx.z & 3;

    __shared__ float s_in[18 * 34];
    __shared__ float s_w[32 * 9];

    float acc0[32], acc1[32];
#pragma unroll
    for (int i = 0; i < 32; i++) { acc0[i] = 0.f; acc1[i] = 0.f; }

    for (int ci = 0; ci < CIN; ci++) {
        const float* src = (ci < C) ? (feat + ((size_t)n * C + ci) * HW)
                                    : (wtin + ((size_t)n * CWCH + (ci - C)) * HW);
        for (int idx = threadIdx.x; idx < 18 * 34; idx += 256) {
            int r = idx / 34, cc = idx - r * 34;
            int gh = h0 + r - 1, gw = w0 + cc - 1;
            float v = 0.f;
            if (gh >= 0 && gh < H && gw >= 0 && gw < W) v = src[gh * W + gw];
            s_in[idx] = v;
        }
        for (int idx = threadIdx.x; idx < 288; idx += 256) {
            int co = idx / 9, l = idx - co * 9;
            s_w[idx] = w1[((size_t)(cog * 32 + co) * CIN + ci) * 9 + l];
        }
        __syncthreads();

        float in0[9], in1[9];
#pragma unroll
        for (int i = 0; i < 3; i++)
#pragma unroll
            for (int j = 0; j < 3; j++) {
                in0[i * 3 + j] = s_in[(ty + i) * 34 + tx + j];
                in1[i * 3 + j] = s_in[(ty + 8 + i) * 34 + tx + j];
            }
#pragma unroll
        for (int co = 0; co < 32; co++) {
#pragma unroll
            for (int l = 0; l < 9; l++) {
                float wv = s_w[co * 9 + l];
                acc0[co] = fmaf(in0[l], wv, acc0[co]);
                acc1[co] = fmaf(in1[l], wv, acc1[co]);
            }
        }
        __syncthreads();
    }

#pragma unroll
    for (int co = 0; co < 32; co++) {
        float bb = b1[cog * 32 + co];
        size_t base = ((size_t)n * C + cog * 32 + co) * HW;
        g_hmid[base + (size_t)(h0 + ty) * W + w0 + tx]     = tanhf(acc0[co] + bb);
        g_hmid[base + (size_t)(h0 + ty + 8) * W + w0 + tx] = tanhf(acc1[co] + bb);
    }
}

// ---------------------------------------------------------------------------
// Kernel 2: conv2 1x1 (128 -> 36) + tanh, then bases[m][l] = sum_t b[m,t]*bb[t,l]
// ---------------------------------------------------------------------------
__global__ __launch_bounds__(256) void conv2_bases_kernel(
    const float* __restrict__ w2, const float* __restrict__ b2,
    const float* __restrict__ bb)
{
    __shared__ float s_w2[36 * 128];
    __shared__ float s_b2[36];
    __shared__ float s_bb[54];
    for (int idx = threadIdx.x; idx < 36 * 128; idx += 256) s_w2[idx] = w2[idx];
    if (threadIdx.x < 36) s_b2[threadIdx.x] = b2[threadIdx.x];
    if (threadIdx.x < 54) s_bb[threadIdx.x] = bb[threadIdx.x];
    __syncthreads();

    const int n = blockIdx.y;
    const int p = blockIdx.x * 256 + threadIdx.x;

    float acc[36];
#pragma unroll
    for (int j = 0; j < 36; j++) acc[j] = s_b2[j];

    const float* hm = g_hmid + (size_t)n * C * HW + p;
    for (int c = 0; c < C; c++) {
        float v = hm[(size_t)c * HW];
#pragma unroll
        for (int j = 0; j < 36; j++) acc[j] = fmaf(v, s_w2[j * 128 + c], acc[j]);
    }
#pragma unroll
    for (int j = 0; j < 36; j++) acc[j] = tanhf(acc[j]);

    float* bout = g_bases + (size_t)n * NB * 9 * HW + p;
#pragma unroll
    for (int m = 0; m < NB; m++) {
#pragma unroll
        for (int l = 0; l < 9; l++) {
            float s = 0.f;
#pragma unroll
            for (int t = 0; t < TEM; t++) s = fmaf(acc[m * 6 + t], s_bb[t * 9 + l], s);
            bout[(size_t)(m * 9 + l) * HW] = s;
        }
    }
}

// ---------------------------------------------------------------------------
// Kernel 3 (FUSED stage3+stage4):
//  out[n,co,p] = bias[co] + sum_{c,m} coef[co,c*6+m] * (sum_l bases[m,l,p]*patch(c,l,p))
// Block: 128 px tile (16w x 8h), all 128 couts, one n. 256 threads.
// Phase 1 per 16-ch chunk: bo[c,m,px] -> smem. Phase 2: register GEMM.
// ---------------------------------------------------------------------------
#define KCH 16                 // channels per chunk
#define KLOC (KCH*NB)          // 96 k-values per chunk
#define SM_BASES 0                       // 54*128
#define SM_BO    (SM_BASES + 54*128)     // 96*128
#define SM_FEAT  (SM_BO + KLOC*128)      // 16*180
#define SM_COEF  (SM_FEAT + KCH*180)     // 96*128
#define SM_TOT_F (SM_COEF + KLOC*128)    // floats

__global__ __launch_bounds__(256) void fused_kernel(
    const float* __restrict__ feat, const float* __restrict__ bias,
    float* __restrict__ out)
{
    extern __shared__ float sm[];
    const int tid = threadIdx.x;
    const int blk = blockIdx.x;
    const int n = blk / 72;
    const int t = blk - n * 72;
    const int ty0 = (t / 6) * 8;
    const int tx0 = (t - (t / 6) * 6) * 16;

    // Stage per-pixel bases (54 x 128 px) once
    {
        const float* bsrc = g_bases + (size_t)n * 54 * HW;
        for (int idx = tid; idx < 54 * 128; idx += 256) {
            int j = idx >> 7, px = idx & 127;
            int y = px >> 4, x = px & 15;
            sm[SM_BASES + idx] = bsrc[(size_t)j * HW + (ty0 + y) * W + tx0 + x];
        }
    }

    const int q  = tid >> 6;          // cout quarter 0..3
    const int pp = tid & 63;          // pixel pair
    const int px0 = pp * 2;

    float acc0[32], acc1[32];
#pragma unroll
    for (int i = 0; i < 32; i++) { acc0[i] = 0.f; acc1[i] = 0.f; }

    for (int cc0 = 0; cc0 < C; cc0 += KCH) {
        __syncthreads();
        // stage feat halo tile: KCH channels x 10 rows x 18 cols
        for (int idx = tid; idx < KCH * 180; idx += 256) {
            int c = idx / 180, rem = idx - c * 180;
            int r = rem / 18, col = rem - r * 18;
            int gh = ty0 + r - 1, gw = tx0 + col - 1;
            float v = 0.f;
            if (gh >= 0 && gh < H && gw >= 0 && gw < W)
                v = feat[((size_t)n * C + cc0 + c) * HW + gh * W + gw];
            sm[SM_FEAT + idx] = v;
        }
        // stage coefT chunk: [96 k][128 co]
        {
            const float* csrc = g_coefT + (size_t)cc0 * NB * C;
            for (int idx = tid; idx < KLOC * 128; idx += 256)
                sm[SM_COEF + idx] = csrc[idx];
        }
        __syncthreads();

        // phase 1: bo[c,m,px]
#pragma unroll
        for (int i = 0; i < 8; i++) {
            int item = i * 256 + tid;          // 2048 items
            int c = item >> 7, px = item & 127;
            int y = px >> 4, x = px & 15;
            float p[9];
            const float* fb = &sm[SM_FEAT + c * 180 + y * 18 + x];
#pragma unroll
            for (int dy = 0; dy < 3; dy++)
#pragma unroll
                for (int dx = 0; dx < 3; dx++) p[dy * 3 + dx] = fb[dy * 18 + dx];
#pragma unroll
            for (int m = 0; m < NB; m++) {
                float s = 0.f;
#pragma unroll
                for (int l = 0; l < 9; l++)
                    s = fmaf(sm[SM_BASES + (m * 9 + l) * 128 + px], p[l], s);
                sm[SM_BO + (c * NB + m) * 128 + px] = s;
            }
        }
        __syncthreads();

        // phase 2: acc[co] += coef[k][co] * bo[k][px]
#pragma unroll 4
        for (int kk = 0; kk < KLOC; kk++) {
            float2 b = *(const float2*)&sm[SM_BO + kk * 128 + px0];
            const float* cw = &sm[SM_COEF + kk * 128 + q * 32];
#pragma unroll
            for (int j = 0; j < 8; j++) {
                float4 w = *(const float4*)&cw[j * 4];
                acc0[j*4+0] = fmaf(b.x, w.x, acc0[j*4+0]);
                acc0[j*4+1] = fmaf(b.x, w.y, acc0[j*4+1]);
                acc0[j*4+2] = fmaf(b.x, w.z, acc0[j*4+2]);
                acc0[j*4+3] = fmaf(b.x, w.w, acc0[j*4+3]);
                acc1[j*4+0] = fmaf(b.y, w.x, acc1[j*4+0]);
                acc1[j*4+1] = fmaf(b.y, w.y, acc1[j*4+1]);
                acc1[j*4+2] = fmaf(b.y, w.z, acc1[j*4+2]);
                acc1[j*4+3] = fmaf(b.y, w.w, acc1[j*4+3]);
            }
        }
    }

    // epilogue
    const int y0 = px0 >> 4, x0 = px0 & 15;      // x0 even, pair in same row
    const int gpix = (ty0 + y0) * W + tx0 + x0;
#pragma unroll
    for (int j = 0; j < 32; j++) {
        int co = q * 32 + j;
        float bv = bias[co];
        float2 v; v.x = acc0[j] + bv; v.y = acc1[j] + bv;
        *(float2*)&out[((size_t)n * C + co) * HW + gpix] = v;
    }
}

// ---------------------------------------------------------------------------
extern "C" void kernel_launch(void* const* d_in, const int* in_sizes, int n_in,
                              void* d_out, int out_size)
{
    const float* feat  = (const float*)d_in[0];
    const float* wtin  = (const float*)d_in[1];
    const float* w1    = (const float*)d_in[2];
    const float* b1    = (const float*)d_in[3];
    const float* w2    = (const float*)d_in[4];
    const float* b2    = (const float*)d_in[5];
    const float* bb    = (const float*)d_in[6];
    const float* coef  = (const float*)d_in[7];
    const float* bias  = (const float*)d_in[8];
    float* out = (float*)d_out;

    cudaFuncSetAttribute(fused_kernel,
        cudaFuncAttributeMaxDynamicSharedMemorySize, SM_TOT_F * (int)sizeof(float));

    coefT_kernel<<<KTOT * C / 256, 256>>>(coef);
    conv1_kernel<<<dim3(3, 6, NN * 4), 256>>>(feat, wtin, w1, b1);
    conv2_bases_kernel<<<dim3(HW / 256, NN), 256>>>(w2, b2, bb);
    fused_kernel<<<NN * 72, 256, SM_TOT_F * sizeof(float)>>>(feat, bias, out);
}

// round 10
// speedup vs baseline: 2.1407x; 1.7346x over previous
#include <cuda_runtime.h>
#include <cuda_bf16.h>
#include <stdint.h>
#include <math.h>

#define NN 8
#define C 128
#define CWCH 64
#define H 96
#define W 96
#define HW (H*W)
#define CIN 192
#define NB 6
#define TEM 6
#define KTOT (C*NB)          // 768
#define K1 (CIN*9)           // 1728
#define KC 64
#define NCHUNK (K1/KC)       // 27

// Scratch (allocation-free rule: __device__ globals)
__device__ float g_hmid[(size_t)NN*C*HW];              // 37.7 MB
__device__ float g_bases[(size_t)NN*NB*9*HW];          // 15.9 MB
__device__ float g_coefT[(size_t)KTOT*C];              // 393 KB
__device__ __nv_bfloat16 g_w1hi[(size_t)C*K1];         // 432 KB
__device__ __nv_bfloat16 g_w1lo[(size_t)C*K1];         // 432 KB
__device__ uint32_t g_fpack[(size_t)NN*CIN*HW];        // 56.6 MB (hi | lo<<16)

// ---------------------------------------------------------------------------
__device__ __forceinline__ uint32_t smem_u32(const void* p) {
    uint32_t a;
    asm("{ .reg .u64 t; cvta.to.shared.u64 t, %1; cvt.u32.u64 %0, t; }"
        : "=r"(a) : "l"(p));
    return a;
}

#define LDSM_X4(r0,r1,r2,r3, addr) \
    asm volatile("ldmatrix.sync.aligned.m8n8.x4.shared.b16 {%0,%1,%2,%3}, [%4];" \
        : "=r"(r0), "=r"(r1), "=r"(r2), "=r"(r3) : "r"(addr))

#define MMA_BF16(d, a, b) \
    asm volatile("mma.sync.aligned.m16n8k16.row.col.f32.bf16.bf16.f32 " \
        "{%0,%1,%2,%3}, {%4,%5,%6,%7}, {%8,%9}, {%0,%1,%2,%3};" \
        : "+f"((d)[0]), "+f"((d)[1]), "+f"((d)[2]), "+f"((d)[3]) \
        : "r"((a)[0]), "r"((a)[1]), "r"((a)[2]), "r"((a)[3]), \
          "r"((b)[0]), "r"((b)[1]))

__device__ __forceinline__ uint16_t bf_bits(__nv_bfloat16 h) {
    return *reinterpret_cast<const uint16_t*>(&h);
}

// ---------------------------------------------------------------------------
// Prep A: split conv1 weights into bf16 hi/lo
// ---------------------------------------------------------------------------
__global__ __launch_bounds__(256) void w1split_kernel(const float* __restrict__ w1)
{
    int idx = blockIdx.x * 256 + threadIdx.x;
    if (idx >= C * K1) return;
    float v = w1[idx];
    __nv_bfloat16 hi = __float2bfloat16(v);
    __nv_bfloat16 lo = __float2bfloat16(v - __bfloat162float(hi));
    g_w1hi[idx] = hi;
    g_w1lo[idx] = lo;
}

// ---------------------------------------------------------------------------
// Prep B: pack concat(feat,weight) into (bf16 hi | bf16 lo << 16)
// ---------------------------------------------------------------------------
__global__ __launch_bounds__(256) void fpack_kernel(
    const float* __restrict__ feat, const float* __restrict__ wtin)
{
    size_t idx = (size_t)blockIdx.x * 256 + threadIdx.x;
    if (idx >= (size_t)NN * CIN * HW) return;
    int n = (int)(idx / ((size_t)CIN * HW));
    int r = (int)(idx - (size_t)n * CIN * HW);
    int ci = r / HW, p = r - ci * HW;
    float v = (ci < C) ? feat[((size_t)n * C + ci) * HW + p]
                       : wtin[((size_t)n * CWCH + (ci - C)) * HW + p];
    __nv_bfloat16 hi = __float2bfloat16(v);
    __nv_bfloat16 lo = __float2bfloat16(v - __bfloat162float(hi));
    g_fpack[idx] = (uint32_t)bf_bits(hi) | ((uint32_t)bf_bits(lo) << 16);
}

// ---------------------------------------------------------------------------
// Kernel 0: transpose coef (co-major -> k-major)
// ---------------------------------------------------------------------------
__global__ __launch_bounds__(256) void coefT_kernel(const float* __restrict__ coef)
{
    int idx = blockIdx.x * 256 + threadIdx.x;
    int co = idx / KTOT, k = idx - co * KTOT;
    g_coefT[(size_t)k * C + co] = coef[idx];
}

// ---------------------------------------------------------------------------
// conv1 via mma.sync bf16 (3-term split). CTA: 128px (16x8) x 128 couts.
// smem byte offsets:
#define SA_HI 0
#define SA_LO 16384
#define SB_HI 32768
#define SB_LO 49152
#define SHALO 65536                  // uint32[1440]
#define SKTAB (SHALO + 5760)         // int32[64]
#define SBIAS (SKTAB + 256)          // float[128]
#define C1_SMEM (SBIAS + 512)        // 72576 bytes
// ---------------------------------------------------------------------------
__global__ __launch_bounds__(256) void conv1_mma_kernel(const float* __restrict__ b1)
{
    extern __shared__ char smc[];
    const uint32_t sb = smem_u32(smc);
    uint32_t* halo = (uint32_t*)(smc + SHALO);
    int*      ktab = (int*)(smc + SKTAB);
    float*  s_bias = (float*)(smc + SBIAS);

    const int tid = threadIdx.x;
    const int w   = tid >> 5;
    const int lane = tid & 31;
    const int blk = blockIdx.x;
    const int n = blk / 72;
    const int t = blk - n * 72;
    const int ty0 = (t / 6) * 8;
    const int tx0 = (t - (t / 6) * 6) * 16;

    if (tid < C) s_bias[tid] = b1[tid];

    const int mbase = (w & 3) * 32;
    const int nbase = (w >> 2) * 64;

    float d[2][8][4];
#pragma unroll
    for (int mt = 0; mt < 2; mt++)
#pragma unroll
        for (int nt = 0; nt < 8; nt++)
#pragma unroll
            for (int j = 0; j < 4; j++) d[mt][nt][j] = 0.f;

    // per-thread invariant ldmatrix address pieces
    const int rA  = lane & 15;            // row within m16
    const int hiA = lane >> 4;            // k-chunk select (0/1)
    const int rBl = (lane & 7) + ((lane >> 4) << 3);  // row-within-16 for B x4
    const int hiB = (lane >> 3) & 1;

    const uint4* w1hi4 = (const uint4*)g_w1hi;
    const uint4* w1lo4 = (const uint4*)g_w1lo;

    for (int ch = 0; ch < NCHUNK; ch++) {
        const int k0 = ch * KC;
        const int cb = k0 / 9;
        __syncthreads();            // prev MMA done with smem

        // k -> halo-offset table
        if (tid < KC) {
            int k = k0 + tid;
            int ci = k / 9, l = k - ci * 9, dy = l / 3, dx = l - dy * 3;
            ktab[tid] = (ci - cb) * 180 + dy * 18 + dx;
        }
        // halo: 8 channels x 10 x 18 packed bf16 pairs
        for (int idx = tid; idx < 8 * 180; idx += 256) {
            int cc = idx / 180, rem = idx - cc * 180;
            int r = rem / 18, col = rem - r * 18;
            int gh = ty0 + r - 1, gw = tx0 + col - 1;
            uint32_t v = 0u;
            if (gh >= 0 && gh < H && gw >= 0 && gw < W)
                v = g_fpack[((size_t)n * CIN + cb + cc) * HW + gh * W + gw];
            halo[idx] = v;
        }
        // stage A hi/lo: 128co x 64k bf16, 16B-chunk xor swizzle
        {
            const int kchunk0 = k0 >> 3;     // uint4 index base within row
            uint4* dsthi = (uint4*)(smc + SA_HI);
            uint4* dstlo = (uint4*)(smc + SA_LO);
#pragma unroll
            for (int i = 0; i < 4; i++) {
                int idx = i * 256 + tid;     // 1024 = 128co x 8 chunks
                int co = idx >> 3, j = idx & 7;
                int dst = co * 8 + (j ^ (co & 7));
                dsthi[dst] = w1hi4[(size_t)co * (K1 / 8) + kchunk0 + j];
                dstlo[dst] = w1lo4[(size_t)co * (K1 / 8) + kchunk0 + j];
            }
        }
        __syncthreads();

        // build B hi/lo: [px][k] bf16, swizzled; pairs of k per 32-bit store
#pragma unroll
        for (int i = 0; i < 16; i++) {
            int it = i * 256 + tid;          // 4096 = 128px x 32 kpairs
            int px = it >> 5, kp = it & 31;
            int kl = kp * 2;
            int pbase = (px >> 4) * 18 + (px & 15);
            uint32_t h0 = halo[ktab[kl] + pbase];
            uint32_t h1 = halo[ktab[kl + 1] + pbase];
            uint32_t hi = (h0 & 0xFFFFu) | (h1 << 16);
            uint32_t lo = (h0 >> 16) | (h1 & 0xFFFF0000u);
            uint32_t off = (uint32_t)(px * 128 + ((((kl >> 3) ^ (px & 7)) << 4)) + ((kl & 7) << 1));
            *(uint32_t*)(smc + SB_HI + off) = hi;
            *(uint32_t*)(smc + SB_LO + off) = lo;
        }
        __syncthreads();

        // MMA: 4 k16 steps x (Ahi*Bhi + Ahi*Blo + Alo*Bhi)
#pragma unroll
        for (int kt = 0; kt < 4; kt++) {
            uint32_t ah[2][4], bh[8][2];
            // A hi fragments
#pragma unroll
            for (int mt = 0; mt < 2; mt++) {
                int row = mbase + mt * 16 + rA;
                uint32_t addr = sb + SA_HI + row * 128
                              + ((((kt * 2 + hiA) ^ (rA & 7))) << 4);
                LDSM_X4(ah[mt][0], ah[mt][1], ah[mt][2], ah[mt][3], addr);
            }
            // B hi fragments (4 x4 -> 8 n-tiles)
#pragma unroll
            for (int np = 0; np < 4; np++) {
                int row = nbase + np * 16 + rBl;
                uint32_t addr = sb + SB_HI + row * 128
                              + ((((kt * 2 + hiB) ^ (row & 7))) << 4);
                LDSM_X4(bh[2*np][0], bh[2*np][1], bh[2*np+1][0], bh[2*np+1][1], addr);
            }
#pragma unroll
            for (int mt = 0; mt < 2; mt++)
#pragma unroll
                for (int nt = 0; nt < 8; nt++) MMA_BF16(d[mt][nt], ah[mt], bh[nt]);
            // B lo
            {
                uint32_t bl[8][2];
#pragma unroll
                for (int np = 0; np < 4; np++) {
                    int row = nbase + np * 16 + rBl;
                    uint32_t addr = sb + SB_LO + row * 128
                                  + ((((kt * 2 + hiB) ^ (row & 7))) << 4);
                    LDSM_X4(bl[2*np][0], bl[2*np][1], bl[2*np+1][0], bl[2*np+1][1], addr);
                }
#pragma unroll
                for (int mt = 0; mt < 2; mt++)
#pragma unroll
                    for (int nt = 0; nt < 8; nt++) MMA_BF16(d[mt][nt], ah[mt], bl[nt]);
            }
            // A lo
            {
                uint32_t al[2][4];
#pragma unroll
                for (int mt = 0; mt < 2; mt++) {
                    int row = mbase + mt * 16 + rA;
                    uint32_t addr = sb + SA_LO + row * 128
                                  + ((((kt * 2 + hiA) ^ (rA & 7))) << 4);
                    LDSM_X4(al[mt][0], al[mt][1], al[mt][2], al[mt][3], addr);
                }
#pragma unroll
                for (int mt = 0; mt < 2; mt++)
#pragma unroll
                    for (int nt = 0; nt < 8; nt++) MMA_BF16(d[mt][nt], al[mt], bh[nt]);
            }
        }
    }
    __syncthreads();

    // epilogue: tanh(acc + bias) -> g_hmid
#pragma unroll
    for (int mt = 0; mt < 2; mt++) {
#pragma unroll
        for (int nt = 0; nt < 8; nt++) {
            int px = nbase + nt * 8 + 2 * (lane & 3);
            int gp = (ty0 + (px >> 4)) * W + tx0 + (px & 15);
            int co0 = mbase + mt * 16 + (lane >> 2);
            float b0 = s_bias[co0];
            float2 v0;
            v0.x = tanhf(d[mt][nt][0] + b0);
            v0.y = tanhf(d[mt][nt][1] + b0);
            *(float2*)&g_hmid[((size_t)n * C + co0) * HW + gp] = v0;
            int co1 = co0 + 8;
            float b1v = s_bias[co1];
            float2 v1;
            v1.x = tanhf(d[mt][nt][2] + b1v);
            v1.y = tanhf(d[mt][nt][3] + b1v);
            *(float2*)&g_hmid[((size_t)n * C + co1) * HW + gp] = v1;
        }
    }
}

// ---------------------------------------------------------------------------
// Kernel 2: conv2 1x1 (128 -> 36) + tanh, then basis mix
// ---------------------------------------------------------------------------
__global__ __launch_bounds__(256) void conv2_bases_kernel(
    const float* __restrict__ w2, const float* __restrict__ b2,
    const float* __restrict__ bb)
{
    __shared__ float s_w2[36 * 128];
    __shared__ float s_b2[36];
    __shared__ float s_bb[54];
    for (int idx = threadIdx.x; idx < 36 * 128; idx += 256) s_w2[idx] = w2[idx];
    if (threadIdx.x < 36) s_b2[threadIdx.x] = b2[threadIdx.x];
    if (threadIdx.x < 54) s_bb[threadIdx.x] = bb[threadIdx.x];
    __syncthreads();

    const int n = blockIdx.y;
    const int p = blockIdx.x * 256 + threadIdx.x;

    float acc[36];
#pragma unroll
    for (int j = 0; j < 36; j++) acc[j] = s_b2[j];

    const float* hm = g_hmid + (size_t)n * C * HW + p;
    for (int c = 0; c < C; c++) {
        float v = hm[(size_t)c * HW];
#pragma unroll
        for (int j = 0; j < 36; j++) acc[j] = fmaf(v, s_w2[j * 128 + c], acc[j]);
    }
#pragma unroll
    for (int j = 0; j < 36; j++) acc[j] = tanhf(acc[j]);

    float* bout = g_bases + (size_t)n * NB * 9 * HW + p;
#pragma unroll
    for (int m = 0; m < NB; m++) {
#pragma unroll
        for (int l = 0; l < 9; l++) {
            float s = 0.f;
#pragma unroll
            for (int t = 0; t < TEM; t++) s = fmaf(acc[m * 6 + t], s_bb[t * 9 + l], s);
            bout[(size_t)(m * 9 + l) * HW] = s;
        }
    }
}

// ---------------------------------------------------------------------------
// Kernel 3 (FUSED stage3+stage4)
// ---------------------------------------------------------------------------
#define KCH 16
#define KLOC (KCH*NB)
#define SM_BASES 0
#define SM_BO    (SM_BASES + 54*128)
#define SM_FEAT  (SM_BO + KLOC*128)
#define SM_COEF  (SM_FEAT + KCH*180)
#define SM_TOT_F (SM_COEF + KLOC*128)

__global__ __launch_bounds__(256) void fused_kernel(
    const float* __restrict__ feat, const float* __restrict__ bias,
    float* __restrict__ out)
{
    extern __shared__ float sm[];
    const int tid = threadIdx.x;
    const int blk = blockIdx.x;
    const int n = blk / 72;
    const int t = blk - n * 72;
    const int ty0 = (t / 6) * 8;
    const int tx0 = (t - (t / 6) * 6) * 16;

    {
        const float* bsrc = g_bases + (size_t)n * 54 * HW;
        for (int idx = tid; idx < 54 * 128; idx += 256) {
            int j = idx >> 7, px = idx & 127;
            int y = px >> 4, x = px & 15;
            sm[SM_BASES + idx] = bsrc[(size_t)j * HW + (ty0 + y) * W + tx0 + x];
        }
    }

    const int q  = tid >> 6;
    const int pp = tid & 63;
    const int px0 = pp * 2;

    float acc0[32], acc1[32];
#pragma unroll
    for (int i = 0; i < 32; i++) { acc0[i] = 0.f; acc1[i] = 0.f; }

    for (int cc0 = 0; cc0 < C; cc0 += KCH) {
        __syncthreads();
        for (int idx = tid; idx < KCH * 180; idx += 256) {
            int c = idx / 180, rem = idx - c * 180;
            int r = rem / 18, col = rem - r * 18;
            int gh = ty0 + r - 1, gw = tx0 + col - 1;
            float v = 0.f;
            if (gh >= 0 && gh < H && gw >= 0 && gw < W)
                v = feat[((size_t)n * C + cc0 + c) * HW + gh * W + gw];
            sm[SM_FEAT + idx] = v;
        }
        {
            const float* csrc = g_coefT + (size_t)cc0 * NB * C;
            for (int idx = tid; idx < KLOC * 128; idx += 256)
                sm[SM_COEF + idx] = csrc[idx];
        }
        __syncthreads();

#pragma unroll
        for (int i = 0; i < 8; i++) {
            int item = i * 256 + tid;
            int c = item >> 7, px = item & 127;
            int y = px >> 4, x = px & 15;
            float p[9];
            const float* fb = &sm[SM_FEAT + c * 180 + y * 18 + x];
#pragma unroll
            for (int dy = 0; dy < 3; dy++)
#pragma unroll
                for (int dx = 0; dx < 3; dx++) p[dy * 3 + dx] = fb[dy * 18 + dx];
#pragma unroll
            for (int m = 0; m < NB; m++) {
                float s = 0.f;
#pragma unroll
                for (int l = 0; l < 9; l++)
                    s = fmaf(sm[SM_BASES + (m * 9 + l) * 128 + px], p[l], s);
                sm[SM_BO + (c * NB + m) * 128 + px] = s;
            }
        }
        __syncthreads();

#pragma unroll 4
        for (int kk = 0; kk < KLOC; kk++) {
            float2 b = *(const float2*)&sm[SM_BO + kk * 128 + px0];
            const float* cw = &sm[SM_COEF + kk * 128 + q * 32];
#pragma unroll
            for (int j = 0; j < 8; j++) {
                float4 w = *(const float4*)&cw[j * 4];
                acc0[j*4+0] = fmaf(b.x, w.x, acc0[j*4+0]);
                acc0[j*4+1] = fmaf(b.x, w.y, acc0[j*4+1]);
                acc0[j*4+2] = fmaf(b.x, w.z, acc0[j*4+2]);
                acc0[j*4+3] = fmaf(b.x, w.w, acc0[j*4+3]);
                acc1[j*4+0] = fmaf(b.y, w.x, acc1[j*4+0]);
                acc1[j*4+1] = fmaf(b.y, w.y, acc1[j*4+1]);
                acc1[j*4+2] = fmaf(b.y, w.z, acc1[j*4+2]);
                acc1[j*4+3] = fmaf(b.y, w.w, acc1[j*4+3]);
            }
        }
    }

    const int y0 = px0 >> 4, x0 = px0 & 15;
    const int gpix = (ty0 + y0) * W + tx0 + x0;
#pragma unroll
    for (int j = 0; j < 32; j++) {
        int co = q * 32 + j;
        float bv = bias[co];
        float2 v; v.x = acc0[j] + bv; v.y = acc1[j] + bv;
        *(float2*)&out[((size_t)n * C + co) * HW + gpix] = v;
    }
}

// ---------------------------------------------------------------------------
extern "C" void kernel_launch(void* const* d_in, const int* in_sizes, int n_in,
                              void* d_out, int out_size)
{
    const float* feat  = (const float*)d_in[0];
    const float* wtin  = (const float*)d_in[1];
    const float* w1    = (const float*)d_in[2];
    const float* b1    = (const float*)d_in[3];
    const float* w2    = (const float*)d_in[4];
    const float* b2    = (const float*)d_in[5];
    const float* bb    = (const float*)d_in[6];
    const float* coef  = (const float*)d_in[7];
    const float* bias  = (const float*)d_in[8];
    float* out = (float*)d_out;

    cudaFuncSetAttribute(conv1_mma_kernel,
        cudaFuncAttributeMaxDynamicSharedMemorySize, C1_SMEM);
    cudaFuncSetAttribute(fused_kernel,
        cudaFuncAttributeMaxDynamicSharedMemorySize, SM_TOT_F * (int)sizeof(float));

    w1split_kernel<<<(C * K1 + 255) / 256, 256>>>(w1);
    fpack_kernel<<<(int)(((size_t)NN * CIN * HW + 255) / 256), 256>>>(feat, wtin);
    coefT_kernel<<<KTOT * C / 256, 256>>>(coef);
    conv1_mma_kernel<<<NN * 72, 256, C1_SMEM>>>(b1);
    conv2_bases_kernel<<<dim3(HW / 256, NN), 256>>>(w2, b2, bb);
    fused_kernel<<<NN * 72, 256, SM_TOT_F * sizeof(float)>>>(feat, bias, out);
}

// round 11
// speedup vs baseline: 2.9643x; 1.3847x over previous
#include <cuda_runtime.h>
#include <cuda_bf16.h>
#include <stdint.h>
#include <math.h>

#define NN 8
#define C 128
#define CWCH 64
#define H 96
#define W 96
#define HW (H*W)
#define CIN 192
#define NB 6
#define TEM 6
#define KTOT (C*NB)          // 768
#define K1 (CIN*9)           // 1728
#define KC 64
#define NCHUNK (K1/KC)       // 27
#define KPAD 1024            // padded K for final GEMM (128ch x 8m)

// Scratch (allocation-free rule: __device__ globals)
__device__ float g_hmid[(size_t)NN*C*HW];              // 37.7 MB
__device__ float g_bases[(size_t)NN*NB*9*HW];          // 15.9 MB
__device__ __nv_bfloat16 g_w1hi[(size_t)C*K1];         // 432 KB
__device__ __nv_bfloat16 g_w1lo[(size_t)C*K1];         // 432 KB
__device__ uint32_t g_fpack[(size_t)NN*CIN*HW];        // 56.6 MB (hi | lo<<16)
__device__ __nv_bfloat16 g_cAhi[(size_t)C*KPAD];       // 256 KB  [co][c*8+m]
__device__ __nv_bfloat16 g_cAlo[(size_t)C*KPAD];       // 256 KB

// ---------------------------------------------------------------------------
__device__ __forceinline__ uint32_t smem_u32(const void* p) {
    uint32_t a;
    asm("{ .reg .u64 t; cvta.to.shared.u64 t, %1; cvt.u32.u64 %0, t; }"
        : "=r"(a) : "l"(p));
    return a;
}

#define LDSM_X4(r0,r1,r2,r3, addr) \
    asm volatile("ldmatrix.sync.aligned.m8n8.x4.shared.b16 {%0,%1,%2,%3}, [%4];" \
        : "=r"(r0), "=r"(r1), "=r"(r2), "=r"(r3) : "r"(addr))

#define MMA_BF16(d, a, b) \
    asm volatile("mma.sync.aligned.m16n8k16.row.col.f32.bf16.bf16.f32 " \
        "{%0,%1,%2,%3}, {%4,%5,%6,%7}, {%8,%9}, {%0,%1,%2,%3};" \
        : "+f"((d)[0]), "+f"((d)[1]), "+f"((d)[2]), "+f"((d)[3]) \
        : "r"((a)[0]), "r"((a)[1]), "r"((a)[2]), "r"((a)[3]), \
          "r"((b)[0]), "r"((b)[1]))

__device__ __forceinline__ uint16_t bf_bits(__nv_bfloat16 h) {
    return *reinterpret_cast<const uint16_t*>(&h);
}

// ---------------------------------------------------------------------------
// Prep A: split conv1 weights into bf16 hi/lo
// ---------------------------------------------------------------------------
__global__ __launch_bounds__(256) void w1split_kernel(const float* __restrict__ w1)
{
    int idx = blockIdx.x * 256 + threadIdx.x;
    if (idx >= C * K1) return;
    float v = w1[idx];
    __nv_bfloat16 hi = __float2bfloat16(v);
    __nv_bfloat16 lo = __float2bfloat16(v - __bfloat162float(hi));
    g_w1hi[idx] = hi;
    g_w1lo[idx] = lo;
}

// ---------------------------------------------------------------------------
// Prep B: pack concat(feat,weight) into (bf16 hi | bf16 lo << 16)
// ---------------------------------------------------------------------------
__global__ __launch_bounds__(256) void fpack_kernel(
    const float* __restrict__ feat, const float* __restrict__ wtin)
{
    size_t idx = (size_t)blockIdx.x * 256 + threadIdx.x;
    if (idx >= (size_t)NN * CIN * HW) return;
    int n = (int)(idx / ((size_t)CIN * HW));
    int r = (int)(idx - (size_t)n * CIN * HW);
    int ci = r / HW, p = r - ci * HW;
    float v = (ci < C) ? feat[((size_t)n * C + ci) * HW + p]
                       : wtin[((size_t)n * CWCH + (ci - C)) * HW + p];
    __nv_bfloat16 hi = __float2bfloat16(v);
    __nv_bfloat16 lo = __float2bfloat16(v - __bfloat162float(hi));
    g_fpack[idx] = (uint32_t)bf_bits(hi) | ((uint32_t)bf_bits(lo) << 16);
}

// ---------------------------------------------------------------------------
// Prep C: coef -> padded bf16 hi/lo A-matrix  [co][c*8+m], m=6,7 are zero
// ---------------------------------------------------------------------------
__global__ __launch_bounds__(256) void coefA_kernel(const float* __restrict__ coef)
{
    int idx = blockIdx.x * 256 + threadIdx.x;   // 131072
    int co = idx >> 10, k = idx & 1023;
    int c = k >> 3, m = k & 7;
    float v = (m < NB) ? coef[(size_t)co * KTOT + c * NB + m] : 0.f;
    __nv_bfloat16 hi = __float2bfloat16(v);
    __nv_bfloat16 lo = __float2bfloat16(v - __bfloat162float(hi));
    g_cAhi[idx] = hi;
    g_cAlo[idx] = lo;
}

// ---------------------------------------------------------------------------
// conv1 via mma.sync bf16 (3-term split). CTA: 128px (16x8) x 128 couts.
// ---------------------------------------------------------------------------
#define SA_HI 0
#define SA_LO 16384
#define SB_HI 32768
#define SB_LO 49152
#define SHALO 65536                  // uint32[1440]
#define SKTAB (SHALO + 5760)         // int32[64]
#define SBIAS (SKTAB + 256)          // float[128]
#define C1_SMEM (SBIAS + 512)
__global__ __launch_bounds__(256) void conv1_mma_kernel(const float* __restrict__ b1)
{
    extern __shared__ char smc[];
    const uint32_t sb = smem_u32(smc);
    uint32_t* halo = (uint32_t*)(smc + SHALO);
    int*      ktab = (int*)(smc + SKTAB);
    float*  s_bias = (float*)(smc + SBIAS);

    const int tid = threadIdx.x;
    const int w   = tid >> 5;
    const int lane = tid & 31;
    const int blk = blockIdx.x;
    const int n = blk / 72;
    const int t = blk - n * 72;
    const int ty0 = (t / 6) * 8;
    const int tx0 = (t - (t / 6) * 6) * 16;

    if (tid < C) s_bias[tid] = b1[tid];

    const int mbase = (w & 3) * 32;
    const int nbase = (w >> 2) * 64;

    float d[2][8][4];
#pragma unroll
    for (int mt = 0; mt < 2; mt++)
#pragma unroll
        for (int nt = 0; nt < 8; nt++)
#pragma unroll
            for (int j = 0; j < 4; j++) d[mt][nt][j] = 0.f;

    const int rA  = lane & 15;
    const int hiA = lane >> 4;
    const int rBl = (lane & 7) + ((lane >> 4) << 3);
    const int hiB = (lane >> 3) & 1;

    const uint4* w1hi4 = (const uint4*)g_w1hi;
    const uint4* w1lo4 = (const uint4*)g_w1lo;

    for (int ch = 0; ch < NCHUNK; ch++) {
        const int k0 = ch * KC;
        const int cb = k0 / 9;
        __syncthreads();

        if (tid < KC) {
            int k = k0 + tid;
            int ci = k / 9, l = k - ci * 9, dy = l / 3, dx = l - dy * 3;
            ktab[tid] = (ci - cb) * 180 + dy * 18 + dx;
        }
        for (int idx = tid; idx < 8 * 180; idx += 256) {
            int cc = idx / 180, rem = idx - cc * 180;
            int r = rem / 18, col = rem - r * 18;
            int gh = ty0 + r - 1, gw = tx0 + col - 1;
            uint32_t v = 0u;
            if (gh >= 0 && gh < H && gw >= 0 && gw < W)
                v = g_fpack[((size_t)n * CIN + cb + cc) * HW + gh * W + gw];
            halo[idx] = v;
        }
        {
            const int kchunk0 = k0 >> 3;
            uint4* dsthi = (uint4*)(smc + SA_HI);
            uint4* dstlo = (uint4*)(smc + SA_LO);
#pragma unroll
            for (int i = 0; i < 4; i++) {
                int idx = i * 256 + tid;
                int co = idx >> 3, j = idx & 7;
                int dst = co * 8 + (j ^ (co & 7));
                dsthi[dst] = w1hi4[(size_t)co * (K1 / 8) + kchunk0 + j];
                dstlo[dst] = w1lo4[(size_t)co * (K1 / 8) + kchunk0 + j];
            }
        }
        __syncthreads();

#pragma unroll
        for (int i = 0; i < 16; i++) {
            int it = i * 256 + tid;
            int px = it >> 5, kp = it & 31;
            int kl = kp * 2;
            int pbase = (px >> 4) * 18 + (px & 15);
            uint32_t h0 = halo[ktab[kl] + pbase];
            uint32_t h1 = halo[ktab[kl + 1] + pbase];
            uint32_t hi = (h0 & 0xFFFFu) | (h1 << 16);
            uint32_t lo = (h0 >> 16) | (h1 & 0xFFFF0000u);
            uint32_t off = (uint32_t)(px * 128 + ((((kl >> 3) ^ (px & 7)) << 4)) + ((kl & 7) << 1));
            *(uint32_t*)(smc + SB_HI + off) = hi;
            *(uint32_t*)(smc + SB_LO + off) = lo;
        }
        __syncthreads();

#pragma unroll
        for (int kt = 0; kt < 4; kt++) {
            uint32_t ah[2][4], bh[8][2];
#pragma unroll
            for (int mt = 0; mt < 2; mt++) {
                int row = mbase + mt * 16 + rA;
                uint32_t addr = sb + SA_HI + row * 128
                              + ((((kt * 2 + hiA) ^ (rA & 7))) << 4);
                LDSM_X4(ah[mt][0], ah[mt][1], ah[mt][2], ah[mt][3], addr);
            }
#pragma unroll
            for (int np = 0; np < 4; np++) {
                int row = nbase + np * 16 + rBl;
                uint32_t addr = sb + SB_HI + row * 128
                              + ((((kt * 2 + hiB) ^ (row & 7))) << 4);
                LDSM_X4(bh[2*np][0], bh[2*np][1], bh[2*np+1][0], bh[2*np+1][1], addr);
            }
#pragma unroll
            for (int mt = 0; mt < 2; mt++)
#pragma unroll
                for (int nt = 0; nt < 8; nt++) MMA_BF16(d[mt][nt], ah[mt], bh[nt]);
            {
                uint32_t bl[8][2];
#pragma unroll
                for (int np = 0; np < 4; np++) {
                    int row = nbase + np * 16 + rBl;
                    uint32_t addr = sb + SB_LO + row * 128
                                  + ((((kt * 2 + hiB) ^ (row & 7))) << 4);
                    LDSM_X4(bl[2*np][0], bl[2*np][1], bl[2*np+1][0], bl[2*np+1][1], addr);
                }
#pragma unroll
                for (int mt = 0; mt < 2; mt++)
#pragma unroll
                    for (int nt = 0; nt < 8; nt++) MMA_BF16(d[mt][nt], ah[mt], bl[nt]);
            }
            {
                uint32_t al[2][4];
#pragma unroll
                for (int mt = 0; mt < 2; mt++) {
                    int row = mbase + mt * 16 + rA;
                    uint32_t addr = sb + SA_LO + row * 128
                                  + ((((kt * 2 + hiA) ^ (rA & 7))) << 4);
                    LDSM_X4(al[mt][0], al[mt][1], al[mt][2], al[mt][3], addr);
                }
#pragma unroll
                for (int mt = 0; mt < 2; mt++)
#pragma unroll
                    for (int nt = 0; nt < 8; nt++) MMA_BF16(d[mt][nt], al[mt], bh[nt]);
            }
        }
    }
    __syncthreads();

#pragma unroll
    for (int mt = 0; mt < 2; mt++) {
#pragma unroll
        for (int nt = 0; nt < 8; nt++) {
            int px = nbase + nt * 8 + 2 * (lane & 3);
            int gp = (ty0 + (px >> 4)) * W + tx0 + (px & 15);
            int co0 = mbase + mt * 16 + (lane >> 2);
            float b0 = s_bias[co0];
            float2 v0;
            v0.x = tanhf(d[mt][nt][0] + b0);
            v0.y = tanhf(d[mt][nt][1] + b0);
            *(float2*)&g_hmid[((size_t)n * C + co0) * HW + gp] = v0;
            int co1 = co0 + 8;
            float b1v = s_bias[co1];
            float2 v1;
            v1.x = tanhf(d[mt][nt][2] + b1v);
            v1.y = tanhf(d[mt][nt][3] + b1v);
            *(float2*)&g_hmid[((size_t)n * C + co1) * HW + gp] = v1;
        }
    }
}

// ---------------------------------------------------------------------------
// Kernel 2: conv2 1x1 (128 -> 36) + tanh, then basis mix
// ---------------------------------------------------------------------------
__global__ __launch_bounds__(256) void conv2_bases_kernel(
    const float* __restrict__ w2, const float* __restrict__ b2,
    const float* __restrict__ bb)
{
    __shared__ float s_w2[36 * 128];
    __shared__ float s_b2[36];
    __shared__ float s_bb[54];
    for (int idx = threadIdx.x; idx < 36 * 128; idx += 256) s_w2[idx] = w2[idx];
    if (threadIdx.x < 36) s_b2[threadIdx.x] = b2[threadIdx.x];
    if (threadIdx.x < 54) s_bb[threadIdx.x] = bb[threadIdx.x];
    __syncthreads();

    const int n = blockIdx.y;
    const int p = blockIdx.x * 256 + threadIdx.x;

    float acc[36];
#pragma unroll
    for (int j = 0; j < 36; j++) acc[j] = s_b2[j];

    const float* hm = g_hmid + (size_t)n * C * HW + p;
    for (int c = 0; c < C; c++) {
        float v = hm[(size_t)c * HW];
#pragma unroll
        for (int j = 0; j < 36; j++) acc[j] = fmaf(v, s_w2[j * 128 + c], acc[j]);
    }
#pragma unroll
    for (int j = 0; j < 36; j++) acc[j] = tanhf(acc[j]);

    float* bout = g_bases + (size_t)n * NB * 9 * HW + p;
#pragma unroll
    for (int m = 0; m < NB; m++) {
#pragma unroll
        for (int l = 0; l < 9; l++) {
            float s = 0.f;
#pragma unroll
            for (int t = 0; t < TEM; t++) s = fmaf(acc[m * 6 + t], s_bb[t * 9 + l], s);
            bout[(size_t)(m * 9 + l) * HW] = s;
        }
    }
}

// ---------------------------------------------------------------------------
// Kernel 3 (FUSED stage3+stage4, tensor-core): per CTA 128px x 128co,
// K' = 1024 (128ch x 8m padded) in 8 chunks of 128k.
// ---------------------------------------------------------------------------
#define FA_HI  0
#define FA_LO  32768
#define FB_HI  65536
#define FB_LO  98304
#define FBAS   131072     // float[54*128]
#define FHALO  158720     // float[16*180]
#define FBIAS  170240     // float[128]
#define F_SMEM (FBIAS + 512)   // 170752 bytes

__global__ __launch_bounds__(256) void fused_mma_kernel(
    const float* __restrict__ feat, const float* __restrict__ bias,
    float* __restrict__ out)
{
    extern __shared__ char smc[];
    const uint32_t sb = smem_u32(smc);
    float* s_bases = (float*)(smc + FBAS);
    float* s_halo  = (float*)(smc + FHALO);
    float* s_bias  = (float*)(smc + FBIAS);

    const int tid = threadIdx.x;
    const int w   = tid >> 5;
    const int lane = tid & 31;
    const int blk = blockIdx.x;
    const int n = blk / 72;
    const int t = blk - n * 72;
    const int ty0 = (t / 6) * 8;
    const int tx0 = (t - (t / 6) * 6) * 16;

    if (tid < C) s_bias[tid] = bias[tid];
    // stage per-pixel bases (54 x 128) once
    {
        const float* bsrc = g_bases + (size_t)n * 54 * HW;
        for (int idx = tid; idx < 54 * 128; idx += 256) {
            int j = idx >> 7, px = idx & 127;
            int y = px >> 4, x = px & 15;
            s_bases[idx] = bsrc[(size_t)j * HW + (ty0 + y) * W + tx0 + x];
        }
    }

    const int mbase = (w & 3) * 32;
    const int nbase = (w >> 2) * 64;
    const int rA  = lane & 15;
    const int hiA = lane >> 4;
    const int rBl = (lane & 7) + ((lane >> 4) << 3);
    const int hiB = (lane >> 3) & 1;

    float d[2][8][4];
#pragma unroll
    for (int mt = 0; mt < 2; mt++)
#pragma unroll
        for (int nt = 0; nt < 8; nt++)
#pragma unroll
            for (int j = 0; j < 4; j++) d[mt][nt][j] = 0.f;

    const uint4* cAhi4 = (const uint4*)g_cAhi;
    const uint4* cAlo4 = (const uint4*)g_cAlo;

    for (int ch = 0; ch < 8; ch++) {       // 16 channels per chunk, K=128
        const int cb = ch * 16;
        __syncthreads();

        // stage fp32 halo: 16 ch x 10 x 18
        for (int idx = tid; idx < 16 * 180; idx += 256) {
            int cc = idx / 180, rem = idx - cc * 180;
            int r = rem / 18, col = rem - r * 18;
            int gh = ty0 + r - 1, gw = tx0 + col - 1;
            float v = 0.f;
            if (gh >= 0 && gh < H && gw >= 0 && gw < W)
                v = feat[((size_t)n * C + cb + cc) * HW + gh * W + gw];
            s_halo[idx] = v;
        }
        // stage A hi/lo: [128 co][128 k], rows 256B = 16 uint4 chunks, swizzled
        {
            const int kchunk0 = (ch * 128) >> 3;   // uint4 base within co row
            uint4* dsthi = (uint4*)(smc + FA_HI);
            uint4* dstlo = (uint4*)(smc + FA_LO);
#pragma unroll
            for (int i = 0; i < 8; i++) {
                int idx = i * 256 + tid;           // 2048 = 128co x 16 chunks
                int co = idx >> 4, j = idx & 15;
                int dst = co * 16 + (j ^ (co & 7));
                dsthi[dst] = cAhi4[(size_t)co * (KPAD / 8) + kchunk0 + j];
                dstlo[dst] = cAlo4[(size_t)co * (KPAD / 8) + kchunk0 + j];
            }
        }
        __syncthreads();

        // phase 1: bo for (c,px), 6 real m -> bf16 pairs into B tiles
#pragma unroll
        for (int i = 0; i < 8; i++) {
            int it = i * 256 + tid;                // 2048 = 16c x 128px
            int c = it >> 7, px = it & 127;
            int y = px >> 4, x = px & 15;
            float p[9];
            const float* fb = &s_halo[c * 180 + y * 18 + x];
#pragma unroll
            for (int dy = 0; dy < 3; dy++)
#pragma unroll
                for (int dx = 0; dx < 3; dx++) p[dy * 3 + dx] = fb[dy * 18 + dx];
            uint32_t rowoff = (uint32_t)(px * 256 + ((c ^ (px & 7)) << 4));
            float bo[NB];
#pragma unroll
            for (int m = 0; m < NB; m++) {
                float s = 0.f;
#pragma unroll
                for (int l = 0; l < 9; l++)
                    s = fmaf(s_bases[(m * 9 + l) * 128 + px], p[l], s);
                bo[m] = s;
            }
#pragma unroll
            for (int mp = 0; mp < 3; mp++) {
                float v0 = bo[2 * mp], v1 = bo[2 * mp + 1];
                __nv_bfloat16 h0 = __float2bfloat16(v0), h1 = __float2bfloat16(v1);
                uint32_t hi = (uint32_t)bf_bits(h0) | ((uint32_t)bf_bits(h1) << 16);
                __nv_bfloat16 l0 = __float2bfloat16(v0 - __bfloat162float(h0));
                __nv_bfloat16 l1 = __float2bfloat16(v1 - __bfloat162float(h1));
                uint32_t lo = (uint32_t)bf_bits(l0) | ((uint32_t)bf_bits(l1) << 16);
                *(uint32_t*)(smc + FB_HI + rowoff + 4 * mp) = hi;
                *(uint32_t*)(smc + FB_LO + rowoff + 4 * mp) = lo;
            }
            *(uint32_t*)(smc + FB_HI + rowoff + 12) = 0u;   // m=6,7 pad
            *(uint32_t*)(smc + FB_LO + rowoff + 12) = 0u;
        }
        __syncthreads();

        // phase 2: 8 k16 steps x 3 split terms
#pragma unroll
        for (int kt = 0; kt < 8; kt++) {
            uint32_t ah[2][4], bh[8][2];
#pragma unroll
            for (int mt = 0; mt < 2; mt++) {
                int row = mbase + mt * 16 + rA;
                uint32_t addr = sb + FA_HI + row * 256
                              + ((((kt * 2 + hiA) ^ (rA & 7))) << 4);
                LDSM_X4(ah[mt][0], ah[mt][1], ah[mt][2], ah[mt][3], addr);
            }
#pragma unroll
            for (int np = 0; np < 4; np++) {
                int row = nbase + np * 16 + rBl;
                uint32_t addr = sb + FB_HI + row * 256
                              + ((((kt * 2 + hiB) ^ (row & 7))) << 4);
                LDSM_X4(bh[2*np][0], bh[2*np][1], bh[2*np+1][0], bh[2*np+1][1], addr);
            }
#pragma unroll
            for (int mt = 0; mt < 2; mt++)
#pragma unroll
                for (int nt = 0; nt < 8; nt++) MMA_BF16(d[mt][nt], ah[mt], bh[nt]);
            {
                uint32_t bl[8][2];
#pragma unroll
                for (int np = 0; np < 4; np++) {
                    int row = nbase + np * 16 + rBl;
                    uint32_t addr = sb + FB_LO + row * 256
                                  + ((((kt * 2 + hiB) ^ (row & 7))) << 4);
                    LDSM_X4(bl[2*np][0], bl[2*np][1], bl[2*np+1][0], bl[2*np+1][1], addr);
                }
#pragma unroll
                for (int mt = 0; mt < 2; mt++)
#pragma unroll
                    for (int nt = 0; nt < 8; nt++) MMA_BF16(d[mt][nt], ah[mt], bl[nt]);
            }
            {
                uint32_t al[2][4];
#pragma unroll
                for (int mt = 0; mt < 2; mt++) {
                    int row = mbase + mt * 16 + rA;
                    uint32_t addr = sb + FA_LO + row * 256
                                  + ((((kt * 2 + hiA) ^ (rA & 7))) << 4);
                    LDSM_X4(al[mt][0], al[mt][1], al[mt][2], al[mt][3], addr);
                }
#pragma unroll
                for (int mt = 0; mt < 2; mt++)
#pragma unroll
                    for (int nt = 0; nt < 8; nt++) MMA_BF16(d[mt][nt], al[mt], bh[nt]);
            }
        }
    }

    // epilogue: acc + bias -> out
#pragma unroll
    for (int mt = 0; mt < 2; mt++) {
#pragma unroll
        for (int nt = 0; nt < 8; nt++) {
            int px = nbase + nt * 8 + 2 * (lane & 3);
            int gp = (ty0 + (px >> 4)) * W + tx0 + (px & 15);
            int co0 = mbase + mt * 16 + (lane >> 2);
            float b0 = s_bias[co0];
            float2 v0; v0.x = d[mt][nt][0] + b0; v0.y = d[mt][nt][1] + b0;
            *(float2*)&out[((size_t)n * C + co0) * HW + gp] = v0;
            int co1 = co0 + 8;
            float b1v = s_bias[co1];
            float2 v1; v1.x = d[mt][nt][2] + b1v; v1.y = d[mt][nt][3] + b1v;
            *(float2*)&out[((size_t)n * C + co1) * HW + gp] = v1;
        }
    }
}

// ---------------------------------------------------------------------------
extern "C" void kernel_launch(void* const* d_in, const int* in_sizes, int n_in,
                              void* d_out, int out_size)
{
    const float* feat  = (const float*)d_in[0];
    const float* wtin  = (const float*)d_in[1];
    const float* w1    = (const float*)d_in[2];
    const float* b1    = (const float*)d_in[3];
    const float* w2    = (const float*)d_in[4];
    const float* b2    = (const float*)d_in[5];
    const float* bb    = (const float*)d_in[6];
    const float* coef  = (const float*)d_in[7];
    const float* bias  = (const float*)d_in[8];
    float* out = (float*)d_out;

    cudaFuncSetAttribute(conv1_mma_kernel,
        cudaFuncAttributeMaxDynamicSharedMemorySize, C1_SMEM);
    cudaFuncSetAttribute(fused_mma_kernel,
        cudaFuncAttributeMaxDynamicSharedMemorySize, F_SMEM);

    w1split_kernel<<<(C * K1 + 255) / 256, 256>>>(w1);
    fpack_kernel<<<(int)(((size_t)NN * CIN * HW + 255) / 256), 256>>>(feat, wtin);
    coefA_kernel<<<C * KPAD / 256, 256>>>(coef);
    conv1_mma_kernel<<<NN * 72, 256, C1_SMEM>>>(b1);
    conv2_bases_kernel<<<dim3(HW / 256, NN), 256>>>(w2, b2, bb);
    fused_mma_kernel<<<NN * 72, 256, F_SMEM>>>(feat, bias, out);
}

// round 13
// speedup vs baseline: 3.4962x; 1.1794x over previous
#include <cuda_runtime.h>
#include <cuda_bf16.h>
#include <cuda_fp16.h>
#include <stdint.h>
#include <math.h>

#define NN 8
#define C 128
#define CWCH 64
#define H 96
#define W 96
#define HW (H*W)
#define CIN 192
#define NB 6
#define TEM 6
#define KTOT (C*NB)          // 768
#define K1 (CIN*9)           // 1728
#define KC 64
#define NCHUNK (K1/KC)       // 27
#define KPAD 1024            // padded K for final GEMM (128ch x 8m)

// Scratch (allocation-free rule: __device__ globals)
__device__ float g_hmid[(size_t)NN*C*HW];              // 37.7 MB
__device__ float g_bases[(size_t)NN*NB*9*HW];          // 15.9 MB
__device__ __half g_w1h[(size_t)C*K1];                 // 432 KB (fp16)
__device__ uint32_t g_fpack[(size_t)NN*CIN*HW];        // 56.6 MB (fp16 hi | fp16 lo<<16)
__device__ __nv_bfloat16 g_cAhi[(size_t)C*KPAD];       // 256 KB  [co][c*8+m]
__device__ __nv_bfloat16 g_cAlo[(size_t)C*KPAD];       // 256 KB

// ---------------------------------------------------------------------------
__device__ __forceinline__ uint32_t smem_u32(const void* p) {
    uint32_t a;
    asm("{ .reg .u64 t; cvta.to.shared.u64 t, %1; cvt.u32.u64 %0, t; }"
        : "=r"(a) : "l"(p));
    return a;
}

#define LDSM_X4(r0,r1,r2,r3, addr) \
    asm volatile("ldmatrix.sync.aligned.m8n8.x4.shared.b16 {%0,%1,%2,%3}, [%4];" \
        : "=r"(r0), "=r"(r1), "=r"(r2), "=r"(r3) : "r"(addr))

#define MMA_BF16(d, a, b) \
    asm volatile("mma.sync.aligned.m16n8k16.row.col.f32.bf16.bf16.f32 " \
        "{%0,%1,%2,%3}, {%4,%5,%6,%7}, {%8,%9}, {%0,%1,%2,%3};" \
        : "+f"((d)[0]), "+f"((d)[1]), "+f"((d)[2]), "+f"((d)[3]) \
        : "r"((a)[0]), "r"((a)[1]), "r"((a)[2]), "r"((a)[3]), \
          "r"((b)[0]), "r"((b)[1]))

#define MMA_FP16(d, a, b) \
    asm volatile("mma.sync.aligned.m16n8k16.row.col.f32.f16.f16.f32 " \
        "{%0,%1,%2,%3}, {%4,%5,%6,%7}, {%8,%9}, {%0,%1,%2,%3};" \
        : "+f"((d)[0]), "+f"((d)[1]), "+f"((d)[2]), "+f"((d)[3]) \
        : "r"((a)[0]), "r"((a)[1]), "r"((a)[2]), "r"((a)[3]), \
          "r"((b)[0]), "r"((b)[1]))

__device__ __forceinline__ uint16_t bf_bits(__nv_bfloat16 h) {
    return *reinterpret_cast<const uint16_t*>(&h);
}
__device__ __forceinline__ uint16_t hf_bits(__half h) {
    return *reinterpret_cast<const uint16_t*>(&h);
}

// ---------------------------------------------------------------------------
// Prep A: conv1 weights -> fp16
// ---------------------------------------------------------------------------
__global__ __launch_bounds__(256) void w1split_kernel(const float* __restrict__ w1)
{
    int idx = blockIdx.x * 256 + threadIdx.x;
    if (idx >= C * K1) return;
    g_w1h[idx] = __float2half_rn(w1[idx]);
}

// ---------------------------------------------------------------------------
// Prep B: pack concat(feat,weight) into (fp16 hi | fp16 lo << 16)
// ---------------------------------------------------------------------------
__global__ __launch_bounds__(256) void fpack_kernel(
    const float* __restrict__ feat, const float* __restrict__ wtin)
{
    size_t idx = (size_t)blockIdx.x * 256 + threadIdx.x;
    if (idx >= (size_t)NN * CIN * HW) return;
    int n = (int)(idx / ((size_t)CIN * HW));
    int r = (int)(idx - (size_t)n * CIN * HW);
    int ci = r / HW, p = r - ci * HW;
    float v = (ci < C) ? feat[((size_t)n * C + ci) * HW + p]
                       : wtin[((size_t)n * CWCH + (ci - C)) * HW + p];
    __half hi = __float2half_rn(v);
    __half lo = __float2half_rn(v - __half2float(hi));
    g_fpack[idx] = (uint32_t)hf_bits(hi) | ((uint32_t)hf_bits(lo) << 16);
}

// ---------------------------------------------------------------------------
// Prep C: coef -> padded bf16 hi/lo A-matrix  [co][c*8+m], m=6,7 are zero
// ---------------------------------------------------------------------------
__global__ __launch_bounds__(256) void coefA_kernel(const float* __restrict__ coef)
{
    int idx = blockIdx.x * 256 + threadIdx.x;   // 131072
    int co = idx >> 10, k = idx & 1023;
    int c = k >> 3, m = k & 7;
    float v = (m < NB) ? coef[(size_t)co * KTOT + c * NB + m] : 0.f;
    __nv_bfloat16 hi = __float2bfloat16(v);
    __nv_bfloat16 lo = __float2bfloat16(v - __bfloat162float(hi));
    g_cAhi[idx] = hi;
    g_cAlo[idx] = lo;
}

// ---------------------------------------------------------------------------
// conv1 via mma.sync fp16 single-pass. CTA: 128px (16x8) x 128 couts.
// ---------------------------------------------------------------------------
#define SA_HI 0                      // 128co x 64k fp16 = 16384
#define SB_HI 16384                  // 128px x 64k fp16 = 16384
#define SHALO 32768                  // uint32[1440] = 5760
#define SKTAB (SHALO + 5760)         // int32[64]
#define SBIAS (SKTAB + 256)          // float[128]
#define C1_SMEM (SBIAS + 512)        // 39296 bytes
__global__ __launch_bounds__(256) void conv1_mma_kernel(const float* __restrict__ b1)
{
    extern __shared__ char smc[];
    const uint32_t sb = smem_u32(smc);
    uint32_t* halo = (uint32_t*)(smc + SHALO);
    int*      ktab = (int*)(smc + SKTAB);
    float*  s_bias = (float*)(smc + SBIAS);

    const int tid = threadIdx.x;
    const int w   = tid >> 5;
    const int lane = tid & 31;
    const int blk = blockIdx.x;
    const int n = blk / 72;
    const int t = blk - n * 72;
    const int ty0 = (t / 6) * 8;
    const int tx0 = (t - (t / 6) * 6) * 16;

    if (tid < C) s_bias[tid] = b1[tid];

    const int mbase = (w & 3) * 32;
    const int nbase = (w >> 2) * 64;

    float d[2][8][4];
#pragma unroll
    for (int mt = 0; mt < 2; mt++)
#pragma unroll
        for (int nt = 0; nt < 8; nt++)
#pragma unroll
            for (int j = 0; j < 4; j++) d[mt][nt][j] = 0.f;

    const int rA  = lane & 15;
    const int hiA = lane >> 4;
    const int rBl = (lane & 7) + ((lane >> 4) << 3);
    const int hiB = (lane >> 3) & 1;

    const uint4* w1h4 = (const uint4*)g_w1h;

    for (int ch = 0; ch < NCHUNK; ch++) {
        const int k0 = ch * KC;
        const int cb = k0 / 9;
        __syncthreads();

        if (tid < KC) {
            int k = k0 + tid;
            int ci = k / 9, l = k - ci * 9, dy = l / 3, dx = l - dy * 3;
            ktab[tid] = (ci - cb) * 180 + dy * 18 + dx;
        }
        for (int idx = tid; idx < 8 * 180; idx += 256) {
            int cc = idx / 180, rem = idx - cc * 180;
            int r = rem / 18, col = rem - r * 18;
            int gh = ty0 + r - 1, gw = tx0 + col - 1;
            uint32_t v = 0u;
            if (gh >= 0 && gh < H && gw >= 0 && gw < W)
                v = g_fpack[((size_t)n * CIN + cb + cc) * HW + gh * W + gw];
            halo[idx] = v;
        }
        // stage A: 128co x 64k fp16, 16B-chunk xor swizzle
        {
            const int kchunk0 = k0 >> 3;
            uint4* dsthi = (uint4*)(smc + SA_HI);
#pragma unroll
            for (int i = 0; i < 4; i++) {
                int idx = i * 256 + tid;         // 1024 = 128co x 8 chunks
                int co = idx >> 3, j = idx & 7;
                int dst = co * 8 + (j ^ (co & 7));
                dsthi[dst] = w1h4[(size_t)co * (K1 / 8) + kchunk0 + j];
            }
        }
        __syncthreads();

        // build B: [px][k] fp16 (hi halves of packed pairs), swizzled
#pragma unroll
        for (int i = 0; i < 16; i++) {
            int it = i * 256 + tid;              // 4096 = 128px x 32 kpairs
            int px = it >> 5, kp = it & 31;
            int kl = kp * 2;
            int pbase = (px >> 4) * 18 + (px & 15);
            uint32_t h0 = halo[ktab[kl] + pbase];
            uint32_t h1 = halo[ktab[kl + 1] + pbase];
            uint32_t hi = (h0 & 0xFFFFu) | (h1 << 16);
            uint32_t off = (uint32_t)(px * 128 + ((((kl >> 3) ^ (px & 7)) << 4)) + ((kl & 7) << 1));
            *(uint32_t*)(smc + SB_HI + off) = hi;
        }
        __syncthreads();

        // MMA: 4 k16 steps, single fp16 pass
#pragma unroll
        for (int kt = 0; kt < 4; kt++) {
            uint32_t ah[2][4], bh[8][2];
#pragma unroll
            for (int mt = 0; mt < 2; mt++) {
                int row = mbase + mt * 16 + rA;
                uint32_t addr = sb + SA_HI + row * 128
                              + ((((kt * 2 + hiA) ^ (rA & 7))) << 4);
                LDSM_X4(ah[mt][0], ah[mt][1], ah[mt][2], ah[mt][3], addr);
            }
#pragma unroll
            for (int np = 0; np < 4; np++) {
                int row = nbase + np * 16 + rBl;
                uint32_t addr = sb + SB_HI + row * 128
                              + ((((kt * 2 + hiB) ^ (row & 7))) << 4);
                LDSM_X4(bh[2*np][0], bh[2*np][1], bh[2*np+1][0], bh[2*np+1][1], addr);
            }
#pragma unroll
            for (int mt = 0; mt < 2; mt++)
#pragma unroll
                for (int nt = 0; nt < 8; nt++) MMA_FP16(d[mt][nt], ah[mt], bh[nt]);
        }
    }
    __syncthreads();

#pragma unroll
    for (int mt = 0; mt < 2; mt++) {
#pragma unroll
        for (int nt = 0; nt < 8; nt++) {
            int px = nbase + nt * 8 + 2 * (lane & 3);
            int gp = (ty0 + (px >> 4)) * W + tx0 + (px & 15);
            int co0 = mbase + mt * 16 + (lane >> 2);
            float b0 = s_bias[co0];
            float2 v0;
            v0.x = tanhf(d[mt][nt][0] + b0);
            v0.y = tanhf(d[mt][nt][1] + b0);
            *(float2*)&g_hmid[((size_t)n * C + co0) * HW + gp] = v0;
            int co1 = co0 + 8;
            float b1v = s_bias[co1];
            float2 v1;
            v1.x = tanhf(d[mt][nt][2] + b1v);
            v1.y = tanhf(d[mt][nt][3] + b1v);
            *(float2*)&g_hmid[((size_t)n * C + co1) * HW + gp] = v1;
        }
    }
}

// ---------------------------------------------------------------------------
// Kernel 2: conv2 1x1 (128 -> 36) + tanh, then basis mix
// ---------------------------------------------------------------------------
__global__ __launch_bounds__(256) void conv2_bases_kernel(
    const float* __restrict__ w2, const float* __restrict__ b2,
    const float* __restrict__ bb)
{
    __shared__ float s_w2[36 * 128];
    __shared__ float s_b2[36];
    __shared__ float s_bb[54];
    for (int idx = threadIdx.x; idx < 36 * 128; idx += 256) s_w2[idx] = w2[idx];
    if (threadIdx.x < 36) s_b2[threadIdx.x] = b2[threadIdx.x];
    if (threadIdx.x < 54) s_bb[threadIdx.x] = bb[threadIdx.x];
    __syncthreads();

    const int n = blockIdx.y;
    const int p = blockIdx.x * 256 + threadIdx.x;

    float acc[36];
#pragma unroll
    for (int j = 0; j < 36; j++) acc[j] = s_b2[j];

    const float* hm = g_hmid + (size_t)n * C * HW + p;
    for (int c = 0; c < C; c++) {
        float v = hm[(size_t)c * HW];
#pragma unroll
        for (int j = 0; j < 36; j++) acc[j] = fmaf(v, s_w2[j * 128 + c], acc[j]);
    }
#pragma unroll
    for (int j = 0; j < 36; j++) acc[j] = tanhf(acc[j]);

    float* bout = g_bases + (size_t)n * NB * 9 * HW + p;
#pragma unroll
    for (int m = 0; m < NB; m++) {
#pragma unroll
        for (int l = 0; l < 9; l++) {
            float s = 0.f;
#pragma unroll
            for (int t = 0; t < TEM; t++) s = fmaf(acc[m * 6 + t], s_bb[t * 9 + l], s);
            bout[(size_t)(m * 9 + l) * HW] = s;
        }
    }
}

// ---------------------------------------------------------------------------
// Kernel 3 (FUSED stage3+stage4, tensor-core, bf16 3-term split)
// ---------------------------------------------------------------------------
#define FA_HI  0
#define FA_LO  32768
#define FB_HI  65536
#define FB_LO  98304
#define FBAS   131072     // float[54*128]
#define FHALO  158720     // float[16*180]
#define FBIAS  170240     // float[128]
#define F_SMEM (FBIAS + 512)   // 170752 bytes

__global__ __launch_bounds__(256) void fused_mma_kernel(
    const float* __restrict__ feat, const float* __restrict__ bias,
    float* __restrict__ out)
{
    extern __shared__ char smc[];
    const uint32_t sb = smem_u32(smc);
    float* s_bases = (float*)(smc + FBAS);
    float* s_halo  = (float*)(smc + FHALO);
    float* s_bias  = (float*)(smc + FBIAS);

    const int tid = threadIdx.x;
    const int w   = tid >> 5;
    const int lane = tid & 31;
    const int blk = blockIdx.x;
    const int n = blk / 72;
    const int t = blk - n * 72;
    const int ty0 = (t / 6) * 8;
    const int tx0 = (t - (t / 6) * 6) * 16;

    if (tid < C) s_bias[tid] = bias[tid];
    {
        const float* bsrc = g_bases + (size_t)n * 54 * HW;
        for (int idx = tid; idx < 54 * 128; idx += 256) {
            int j = idx >> 7, px = idx & 127;
            int y = px >> 4, x = px & 15;
            s_bases[idx] = bsrc[(size_t)j * HW + (ty0 + y) * W + tx0 + x];
        }
    }

    const int mbase = (w & 3) * 32;
    const int nbase = (w >> 2) * 64;
    const int rA  = lane & 15;
    const int hiA = lane >> 4;
    const int rBl = (lane & 7) + ((lane >> 4) << 3);
    const int hiB = (lane >> 3) & 1;

    float d[2][8][4];
#pragma unroll
    for (int mt = 0; mt < 2; mt++)
#pragma unroll
        for (int nt = 0; nt < 8; nt++)
#pragma unroll
            for (int j = 0; j < 4; j++) d[mt][nt][j] = 0.f;

    const uint4* cAhi4 = (const uint4*)g_cAhi;
    const uint4* cAlo4 = (const uint4*)g_cAlo;

    for (int ch = 0; ch < 8; ch++) {
        const int cb = ch * 16;
        __syncthreads();

        for (int idx = tid; idx < 16 * 180; idx += 256) {
            int cc = idx / 180, rem = idx - cc * 180;
            int r = rem / 18, col = rem - r * 18;
            int gh = ty0 + r - 1, gw = tx0 + col - 1;
            float v = 0.f;
            if (gh >= 0 && gh < H && gw >= 0 && gw < W)
                v = feat[((size_t)n * C + cb + cc) * HW + gh * W + gw];
            s_halo[idx] = v;
        }
        {
            const int kchunk0 = (ch * 128) >> 3;
            uint4* dsthi = (uint4*)(smc + FA_HI);
            uint4* dstlo = (uint4*)(smc + FA_LO);
#pragma unroll
            for (int i = 0; i < 8; i++) {
                int idx = i * 256 + tid;
                int co = idx >> 4, j = idx & 15;
                int dst = co * 16 + (j ^ (co & 7));
                dsthi[dst] = cAhi4[(size_t)co * (KPAD / 8) + kchunk0 + j];
                dstlo[dst] = cAlo4[(size_t)co * (KPAD / 8) + kchunk0 + j];
            }
        }
        __syncthreads();

#pragma unroll
        for (int i = 0; i < 8; i++) {
            int it = i * 256 + tid;
            int c = it >> 7, px = it & 127;
            int y = px >> 4, x = px & 15;
            float p[9];
            const float* fb = &s_halo[c * 180 + y * 18 + x];
#pragma unroll
            for (int dy = 0; dy < 3; dy++)
#pragma unroll
                for (int dx = 0; dx < 3; dx++) p[dy * 3 + dx] = fb[dy * 18 + dx];
            uint32_t rowoff = (uint32_t)(px * 256 + ((c ^ (px & 7)) << 4));
            float bo[NB];
#pragma unroll
            for (int m = 0; m < NB; m++) {
                float s = 0.f;
#pragma unroll
                for (int l = 0; l < 9; l++)
                    s = fmaf(s_bases[(m * 9 + l) * 128 + px], p[l], s);
                bo[m] = s;
            }
#pragma unroll
            for (int mp = 0; mp < 3; mp++) {
                float v0 = bo[2 * mp], v1 = bo[2 * mp + 1];
                __nv_bfloat16 h0 = __float2bfloat16(v0), h1 = __float2bfloat16(v1);
                uint32_t hi = (uint32_t)bf_bits(h0) | ((uint32_t)bf_bits(h1) << 16);
                __nv_bfloat16 l0 = __float2bfloat16(v0 - __bfloat162float(h0));
                __nv_bfloat16 l1 = __float2bfloat16(v1 - __bfloat162float(h1));
                uint32_t lo = (uint32_t)bf_bits(l0) | ((uint32_t)bf_bits(l1) << 16);
                *(uint32_t*)(smc + FB_HI + rowoff + 4 * mp) = hi;
                *(uint32_t*)(smc + FB_LO + rowoff + 4 * mp) = lo;
            }
            *(uint32_t*)(smc + FB_HI + rowoff + 12) = 0u;
            *(uint32_t*)(smc + FB_LO + rowoff + 12) = 0u;
        }
        __syncthreads();

#pragma unroll
        for (int kt = 0; kt < 8; kt++) {
            uint32_t ah[2][4], bh[8][2];
#pragma unroll
            for (int mt = 0; mt < 2; mt++) {
                int row = mbase + mt * 16 + rA;
                uint32_t addr = sb + FA_HI + row * 256
                              + ((((kt * 2 + hiA) ^ (rA & 7))) << 4);
                LDSM_X4(ah[mt][0], ah[mt][1], ah[mt][2], ah[mt][3], addr);
            }
#pragma unroll
            for (int np = 0; np < 4; np++) {
                int row = nbase + np * 16 + rBl;
                uint32_t addr = sb + FB_HI + row * 256
                              + ((((kt * 2 + hiB) ^ (row & 7))) << 4);
                LDSM_X4(bh[2*np][0], bh[2*np][1], bh[2*np+1][0], bh[2*np+1][1], addr);
            }
#pragma unroll
            for (int mt = 0; mt < 2; mt++)
#pragma unroll
                for (int nt = 0; nt < 8; nt++) MMA_BF16(d[mt][nt], ah[mt], bh[nt]);
            {
                uint32_t bl[8][2];
#pragma unroll
                for (int np = 0; np < 4; np++) {
                    int row = nbase + np * 16 + rBl;
                    uint32_t addr = sb + FB_LO + row * 256
                                  + ((((kt * 2 + hiB) ^ (row & 7))) << 4);
                    LDSM_X4(bl[2*np][0], bl[2*np][1], bl[2*np+1][0], bl[2*np+1][1], addr);
                }
#pragma unroll
                for (int mt = 0; mt < 2; mt++)
#pragma unroll
                    for (int nt = 0; nt < 8; nt++) MMA_BF16(d[mt][nt], ah[mt], bl[nt]);
            }
            {
                uint32_t al[2][4];
#pragma unroll
                for (int mt = 0; mt < 2; mt++) {
                    int row = mbase + mt * 16 + rA;
                    uint32_t addr = sb + FA_LO + row * 256
                                  + ((((kt * 2 + hiA) ^ (rA & 7))) << 4);
                    LDSM_X4(al[mt][0], al[mt][1], al[mt][2], al[mt][3], addr);
                }
#pragma unroll
                for (int mt = 0; mt < 2; mt++)
#pragma unroll
                    for (int nt = 0; nt < 8; nt++) MMA_BF16(d[mt][nt], al[mt], bh[nt]);
            }
        }
    }

#pragma unroll
    for (int mt = 0; mt < 2; mt++) {
#pragma unroll
        for (int nt = 0; nt < 8; nt++) {
            int px = nbase + nt * 8 + 2 * (lane & 3);
            int gp = (ty0 + (px >> 4)) * W + tx0 + (px & 15);
            int co0 = mbase + mt * 16 + (lane >> 2);
            float b0 = s_bias[co0];
            float2 v0; v0.x = d[mt][nt][0] + b0; v0.y = d[mt][nt][1] + b0;
            *(float2*)&out[((size_t)n * C + co0) * HW + gp] = v0;
            int co1 = co0 + 8;
            float b1v = s_bias[co1];
            float2 v1; v1.x = d[mt][nt][2] + b1v; v1.y = d[mt][nt][3] + b1v;
            *(float2*)&out[((size_t)n * C + co1) * HW + gp] = v1;
        }
    }
}

// ---------------------------------------------------------------------------
extern "C" void kernel_launch(void* const* d_in, const int* in_sizes, int n_in,
                              void* d_out, int out_size)
{
    const float* feat  = (const float*)d_in[0];
    const float* wtin  = (const float*)d_in[1];
    const float* w1    = (const float*)d_in[2];
    const float* b1    = (const float*)d_in[3];
    const float* w2    = (const float*)d_in[4];
    const float* b2    = (const float*)d_in[5];
    const float* bb    = (const float*)d_in[6];
    const float* coef  = (const float*)d_in[7];
    const float* bias  = (const float*)d_in[8];
    float* out = (float*)d_out;

    cudaFuncSetAttribute(conv1_mma_kernel,
        cudaFuncAttributeMaxDynamicSharedMemorySize, C1_SMEM);
    cudaFuncSetAttribute(fused_mma_kernel,
        cudaFuncAttributeMaxDynamicSharedMemorySize, F_SMEM);

    w1split_kernel<<<(C * K1 + 255) / 256, 256>>>(w1);
    fpack_kernel<<<(int)(((size_t)NN * CIN * HW + 255) / 256), 256>>>(feat, wtin);
    coefA_kernel<<<C * KPAD / 256, 256>>>(coef);
    conv1_mma_kernel<<<NN * 72, 256, C1_SMEM>>>(b1);
    conv2_bases_kernel<<<dim3(HW / 256, NN), 256>>>(w2, b2, bb);
    fused_mma_kernel<<<NN * 72, 256, F_SMEM>>>(feat, bias, out);
}

// round 16
// speedup vs baseline: 3.9172x; 1.1204x over previous
#include <cuda_runtime.h>
#include <cuda_bf16.h>
#include <cuda_fp16.h>
#include <stdint.h>
#include <math.h>

#define NN 8
#define C 128
#define CWCH 64
#define H 96
#define W 96
#define HW (H*W)
#define CIN 192
#define NB 6
#define TEM 6
#define KTOT (C*NB)          // 768
#define K1 (CIN*9)           // 1728
#define KC 64
#define NCHUNK (K1/KC)       // 27
#define KPAD 1024            // padded K for final GEMM (128ch x 8m)

// Scratch (allocation-free rule: __device__ globals)
__device__ float g_hmid[(size_t)NN*C*HW];              // 37.7 MB
__device__ float g_bases[(size_t)NN*NB*9*HW];          // 15.9 MB
__device__ __half g_w1h[(size_t)C*K1];                 // 432 KB (fp16)
__device__ uint32_t g_fpack[(size_t)NN*CIN*HW];        // 56.6 MB (fp16 hi | fp16 lo<<16)
__device__ __half g_cAh[(size_t)C*KPAD];               // 256 KB  [co][c*8+m] fp16

// ---------------------------------------------------------------------------
__device__ __forceinline__ uint32_t smem_u32(const void* p) {
    uint32_t a;
    asm("{ .reg .u64 t; cvta.to.shared.u64 t, %1; cvt.u32.u64 %0, t; }"
        : "=r"(a) : "l"(p));
    return a;
}

#define LDSM_X4(r0,r1,r2,r3, addr) \
    asm volatile("ldmatrix.sync.aligned.m8n8.x4.shared.b16 {%0,%1,%2,%3}, [%4];" \
        : "=r"(r0), "=r"(r1), "=r"(r2), "=r"(r3) : "r"(addr))

#define MMA_FP16(d, a, b) \
    asm volatile("mma.sync.aligned.m16n8k16.row.col.f32.f16.f16.f32 " \
        "{%0,%1,%2,%3}, {%4,%5,%6,%7}, {%8,%9}, {%0,%1,%2,%3};" \
        : "+f"((d)[0]), "+f"((d)[1]), "+f"((d)[2]), "+f"((d)[3]) \
        : "r"((a)[0]), "r"((a)[1]), "r"((a)[2]), "r"((a)[3]), \
          "r"((b)[0]), "r"((b)[1]))

__device__ __forceinline__ uint16_t hf_bits(__half h) {
    return *reinterpret_cast<const uint16_t*>(&h);
}

// ---------------------------------------------------------------------------
// Prep A: conv1 weights -> fp16
// ---------------------------------------------------------------------------
__global__ __launch_bounds__(256) void w1split_kernel(const float* __restrict__ w1)
{
    int idx = blockIdx.x * 256 + threadIdx.x;
    if (idx >= C * K1) return;
    g_w1h[idx] = __float2half_rn(w1[idx]);
}

// ---------------------------------------------------------------------------
// Prep B: pack concat(feat,weight) into (fp16 hi | fp16 lo << 16)
// ---------------------------------------------------------------------------
__global__ __launch_bounds__(256) void fpack_kernel(
    const float* __restrict__ feat, const float* __restrict__ wtin)
{
    size_t idx = (size_t)blockIdx.x * 256 + threadIdx.x;
    if (idx >= (size_t)NN * CIN * HW) return;
    int n = (int)(idx / ((size_t)CIN * HW));
    int r = (int)(idx - (size_t)n * CIN * HW);
    int ci = r / HW, p = r - ci * HW;
    float v = (ci < C) ? feat[((size_t)n * C + ci) * HW + p]
                       : wtin[((size_t)n * CWCH + (ci - C)) * HW + p];
    __half hi = __float2half_rn(v);
    __half lo = __float2half_rn(v - __half2float(hi));
    g_fpack[idx] = (uint32_t)hf_bits(hi) | ((uint32_t)hf_bits(lo) << 16);
}

// ---------------------------------------------------------------------------
// Prep C: coef -> padded fp16 A-matrix  [co][c*8+m], m=6,7 are zero
// ---------------------------------------------------------------------------
__global__ __launch_bounds__(256) void coefA_kernel(const float* __restrict__ coef)
{
    int idx = blockIdx.x * 256 + threadIdx.x;   // 131072
    int co = idx >> 10, k = idx & 1023;
    int c = k >> 3, m = k & 7;
    float v = (m < NB) ? coef[(size_t)co * KTOT + c * NB + m] : 0.f;
    g_cAh[idx] = __float2half_rn(v);
}

// ---------------------------------------------------------------------------
// conv1 via mma.sync fp16 single-pass. CTA: 128px (16x8) x 128 couts.
// ---------------------------------------------------------------------------
#define SA_HI 0                      // 128co x 64k fp16 = 16384
#define SB_HI 16384                  // 128px x 64k fp16 = 16384
#define SHALO 32768                  // uint32[1440] = 5760
#define SKTAB (SHALO + 5760)         // int32[64]
#define SBIAS (SKTAB + 256)          // float[128]
#define C1_SMEM (SBIAS + 512)        // 39296 bytes
__global__ __launch_bounds__(256) void conv1_mma_kernel(const float* __restrict__ b1)
{
    extern __shared__ char smc[];
    const uint32_t sb = smem_u32(smc);
    uint32_t* halo = (uint32_t*)(smc + SHALO);
    int*      ktab = (int*)(smc + SKTAB);
    float*  s_bias = (float*)(smc + SBIAS);

    const int tid = threadIdx.x;
    const int w   = tid >> 5;
    const int lane = tid & 31;
    const int blk = blockIdx.x;
    const int n = blk / 72;
    const int t = blk - n * 72;
    const int ty0 = (t / 6) * 8;
    const int tx0 = (t - (t / 6) * 6) * 16;

    if (tid < C) s_bias[tid] = b1[tid];

    const int mbase = (w & 3) * 32;
    const int nbase = (w >> 2) * 64;

    float d[2][8][4];
#pragma unroll
    for (int mt = 0; mt < 2; mt++)
#pragma unroll
        for (int nt = 0; nt < 8; nt++)
#pragma unroll
            for (int j = 0; j < 4; j++) d[mt][nt][j] = 0.f;

    const int rA  = lane & 15;
    const int hiA = lane >> 4;
    const int rBl = (lane & 7) + ((lane >> 4) << 3);
    const int hiB = (lane >> 3) & 1;

    const uint4* w1h4 = (const uint4*)g_w1h;

    for (int ch = 0; ch < NCHUNK; ch++) {
        const int k0 = ch * KC;
        const int cb = k0 / 9;
        __syncthreads();

        if (tid < KC) {
            int k = k0 + tid;
            int ci = k / 9, l = k - ci * 9, dy = l / 3, dx = l - dy * 3;
            ktab[tid] = (ci - cb) * 180 + dy * 18 + dx;
        }
        for (int idx = tid; idx < 8 * 180; idx += 256) {
            int cc = idx / 180, rem = idx - cc * 180;
            int r = rem / 18, col = rem - r * 18;
            int gh = ty0 + r - 1, gw = tx0 + col - 1;
            uint32_t v = 0u;
            if (gh >= 0 && gh < H && gw >= 0 && gw < W)
                v = g_fpack[((size_t)n * CIN + cb + cc) * HW + gh * W + gw];
            halo[idx] = v;
        }
        // stage A: 128co x 64k fp16, 16B-chunk xor swizzle
        {
            const int kchunk0 = k0 >> 3;
            uint4* dsthi = (uint4*)(smc + SA_HI);
#pragma unroll
            for (int i = 0; i < 4; i++) {
                int idx = i * 256 + tid;         // 1024 = 128co x 8 chunks
                int co = idx >> 3, j = idx & 7;
                int dst = co * 8 + (j ^ (co & 7));
                dsthi[dst] = w1h4[(size_t)co * (K1 / 8) + kchunk0 + j];
            }
        }
        __syncthreads();

        // build B: [px][k] fp16 (hi halves of packed pairs), swizzled
#pragma unroll
        for (int i = 0; i < 16; i++) {
            int it = i * 256 + tid;              // 4096 = 128px x 32 kpairs
            int px = it >> 5, kp = it & 31;
            int kl = kp * 2;
            int pbase = (px >> 4) * 18 + (px & 15);
            uint32_t h0 = halo[ktab[kl] + pbase];
            uint32_t h1 = halo[ktab[kl + 1] + pbase];
            uint32_t hi = (h0 & 0xFFFFu) | (h1 << 16);
            uint32_t off = (uint32_t)(px * 128 + ((((kl >> 3) ^ (px & 7)) << 4)) + ((kl & 7) << 1));
            *(uint32_t*)(smc + SB_HI + off) = hi;
        }
        __syncthreads();

        // MMA: 4 k16 steps, single fp16 pass
#pragma unroll
        for (int kt = 0; kt < 4; kt++) {
            uint32_t ah[2][4], bh[8][2];
#pragma unroll
            for (int mt = 0; mt < 2; mt++) {
                int row = mbase + mt * 16 + rA;
                uint32_t addr = sb + SA_HI + row * 128
                              + ((((kt * 2 + hiA) ^ (rA & 7))) << 4);
                LDSM_X4(ah[mt][0], ah[mt][1], ah[mt][2], ah[mt][3], addr);
            }
#pragma unroll
            for (int np = 0; np < 4; np++) {
                int row = nbase + np * 16 + rBl;
                uint32_t addr = sb + SB_HI + row * 128
                              + ((((kt * 2 + hiB) ^ (row & 7))) << 4);
                LDSM_X4(bh[2*np][0], bh[2*np][1], bh[2*np+1][0], bh[2*np+1][1], addr);
            }
#pragma unroll
            for (int mt = 0; mt < 2; mt++)
#pragma unroll
                for (int nt = 0; nt < 8; nt++) MMA_FP16(d[mt][nt], ah[mt], bh[nt]);
        }
    }
    __syncthreads();

#pragma unroll
    for (int mt = 0; mt < 2; mt++) {
#pragma unroll
        for (int nt = 0; nt < 8; nt++) {
            int px = nbase + nt * 8 + 2 * (lane & 3);
            int gp = (ty0 + (px >> 4)) * W + tx0 + (px & 15);
            int co0 = mbase + mt * 16 + (lane >> 2);
            float b0 = s_bias[co0];
            float2 v0;
            v0.x = tanhf(d[mt][nt][0] + b0);
            v0.y = tanhf(d[mt][nt][1] + b0);
            *(float2*)&g_hmid[((size_t)n * C + co0) * HW + gp] = v0;
            int co1 = co0 + 8;
            float b1v = s_bias[co1];
            float2 v1;
            v1.x = tanhf(d[mt][nt][2] + b1v);
            v1.y = tanhf(d[mt][nt][3] + b1v);
            *(float2*)&g_hmid[((size_t)n * C + co1) * HW + gp] = v1;
        }
    }
}

// ---------------------------------------------------------------------------
// Kernel 2: conv2 1x1 (128 -> 36) + tanh, then basis mix
// ---------------------------------------------------------------------------
__global__ __launch_bounds__(256) void conv2_bases_kernel(
    const float* __restrict__ w2, const float* __restrict__ b2,
    const float* __restrict__ bb)
{
    __shared__ float s_w2[36 * 128];
    __shared__ float s_b2[36];
    __shared__ float s_bb[54];
    for (int idx = threadIdx.x; idx < 36 * 128; idx += 256) s_w2[idx] = w2[idx];
    if (threadIdx.x < 36) s_b2[threadIdx.x] = b2[threadIdx.x];
    if (threadIdx.x < 54) s_bb[threadIdx.x] = bb[threadIdx.x];
    __syncthreads();

    const int n = blockIdx.y;
    const int p = blockIdx.x * 256 + threadIdx.x;

    float acc[36];
#pragma unroll
    for (int j = 0; j < 36; j++) acc[j] = s_b2[j];

    const float* hm = g_hmid + (size_t)n * C * HW + p;
    for (int c = 0; c < C; c++) {
        float v = hm[(size_t)c * HW];
#pragma unroll
        for (int j = 0; j < 36; j++) acc[j] = fmaf(v, s_w2[j * 128 + c], acc[j]);
    }
#pragma unroll
    for (int j = 0; j < 36; j++) acc[j] = tanhf(acc[j]);

    float* bout = g_bases + (size_t)n * NB * 9 * HW + p;
#pragma unroll
    for (int m = 0; m < NB; m++) {
#pragma unroll
        for (int l = 0; l < 9; l++) {
            float s = 0.f;
#pragma unroll
            for (int t = 0; t < TEM; t++) s = fmaf(acc[m * 6 + t], s_bb[t * 9 + l], s);
            bout[(size_t)(m * 9 + l) * HW] = s;
        }
    }
}

// ---------------------------------------------------------------------------
// Kernel 3 (FUSED stage3+stage4, tensor-core, fp16 single-pass)
// ---------------------------------------------------------------------------
#define FA_HI  0          // 128co x 128k fp16 = 32768
#define FB_HI  32768      // 128px x 128k fp16 = 32768
#define FBAS   65536      // float[54*128] = 27648
#define FHALO  93184      // float[16*180] = 11520
#define FBIAS  104704     // float[128]
#define F_SMEM (FBIAS + 512)   // 105216 bytes -> 2 CTAs/SM

__global__ __launch_bounds__(256) void fused_mma_kernel(
    const float* __restrict__ feat, const float* __restrict__ bias,
    float* __restrict__ out)
{
    extern __shared__ char smc[];
    const uint32_t sb = smem_u32(smc);
    float* s_bases = (float*)(smc + FBAS);
    float* s_halo  = (float*)(smc + FHALO);
    float* s_bias  = (float*)(smc + FBIAS);

    const int tid = threadIdx.x;
    const int w   = tid >> 5;
    const int lane = tid & 31;
    const int blk = blockIdx.x;
    const int n = blk / 72;
    const int t = blk - n * 72;
    const int ty0 = (t / 6) * 8;
    const int tx0 = (t - (t / 6) * 6) * 16;

    if (tid < C) s_bias[tid] = bias[tid];
    {
        const float* bsrc = g_bases + (size_t)n * 54 * HW;
        for (int idx = tid; idx < 54 * 128; idx += 256) {
            int j = idx >> 7, px = idx & 127;
            int y = px >> 4, x = px & 15;
            s_bases[idx] = bsrc[(size_t)j * HW + (ty0 + y) * W + tx0 + x];
        }
    }

    const int mbase = (w & 3) * 32;
    const int nbase = (w >> 2) * 64;
    const int rA  = lane & 15;
    const int hiA = lane >> 4;
    const int rBl = (lane & 7) + ((lane >> 4) << 3);
    const int hiB = (lane >> 3) & 1;

    float d[2][8][4];
#pragma unroll
    for (int mt = 0; mt < 2; mt++)
#pragma unroll
        for (int nt = 0; nt < 8; nt++)
#pragma unroll
            for (int j = 0; j < 4; j++) d[mt][nt][j] = 0.f;

    const uint4* cAh4 = (const uint4*)g_cAh;

    for (int ch = 0; ch < 8; ch++) {       // 16 channels per chunk, K=128
        const int cb = ch * 16;
        __syncthreads();

        // stage fp32 halo: 16 ch x 10 x 18
        for (int idx = tid; idx < 16 * 180; idx += 256) {
            int cc = idx / 180, rem = idx - cc * 180;
            int r = rem / 18, col = rem - r * 18;
            int gh = ty0 + r - 1, gw = tx0 + col - 1;
            float v = 0.f;
            if (gh >= 0 && gh < H && gw >= 0 && gw < W)
                v = feat[((size_t)n * C + cb + cc) * HW + gh * W + gw];
            s_halo[idx] = v;
        }
        // stage A: [128 co][128 k] fp16, rows 256B = 16 uint4 chunks, swizzled
        {
            const int kchunk0 = (ch * 128) >> 3;
            uint4* dsthi = (uint4*)(smc + FA_HI);
#pragma unroll
            for (int i = 0; i < 8; i++) {
                int idx = i * 256 + tid;           // 2048 = 128co x 16 chunks
                int co = idx >> 4, j = idx & 15;
                int dst = co * 16 + (j ^ (co & 7));
                dsthi[dst] = cAh4[(size_t)co * (KPAD / 8) + kchunk0 + j];
            }
        }
        __syncthreads();

        // phase 1: bo for (c,px), 6 real m -> fp16 pairs into B tile
#pragma unroll
        for (int i = 0; i < 8; i++) {
            int it = i * 256 + tid;                // 2048 = 16c x 128px
            int c = it >> 7, px = it & 127;
            int y = px >> 4, x = px & 15;
            float p[9];
            const float* fb = &s_halo[c * 180 + y * 18 + x];
#pragma unroll
            for (int dy = 0; dy < 3; dy++)
#pragma unroll
                for (int dx = 0; dx < 3; dx++) p[dy * 3 + dx] = fb[dy * 18 + dx];
            uint32_t rowoff = (uint32_t)(px * 256 + ((c ^ (px & 7)) << 4));
            float bo[NB];
#pragma unroll
            for (int m = 0; m < NB; m++) {
                float s = 0.f;
#pragma unroll
                for (int l = 0; l < 9; l++)
                    s = fmaf(s_bases[(m * 9 + l) * 128 + px], p[l], s);
                bo[m] = s;
            }
#pragma unroll
            for (int mp = 0; mp < 3; mp++) {
                __half h0 = __float2half_rn(bo[2 * mp]);
                __half h1 = __float2half_rn(bo[2 * mp + 1]);
                uint32_t hi = (uint32_t)hf_bits(h0) | ((uint32_t)hf_bits(h1) << 16);
                *(uint32_t*)(smc + FB_HI + rowoff + 4 * mp) = hi;
            }
            *(uint32_t*)(smc + FB_HI + rowoff + 12) = 0u;   // m=6,7 pad
        }
        __syncthreads();

        // phase 2: 8 k16 steps, single fp16 pass
#pragma unroll
        for (int kt = 0; kt < 8; kt++) {
            uint32_t ah[2][4], bh[8][2];
#pragma unroll
            for (int mt = 0; mt < 2; mt++) {
                int row = mbase + mt * 16 + rA;
                uint32_t addr = sb + FA_HI + row * 256
                              + ((((kt * 2 + hiA) ^ (rA & 7))) << 4);
                LDSM_X4(ah[mt][0], ah[mt][1], ah[mt][2], ah[mt][3], addr);
            }
#pragma unroll
            for (int np = 0; np < 4; np++) {
                int row = nbase + np * 16 + rBl;
                uint32_t addr = sb + FB_HI + row * 256
                              + ((((kt * 2 + hiB) ^ (row & 7))) << 4);
                LDSM_X4(bh[2*np][0], bh[2*np][1], bh[2*np+1][0], bh[2*np+1][1], addr);
            }
#pragma unroll
            for (int mt = 0; mt < 2; mt++)
#pragma unroll
                for (int nt = 0; nt < 8; nt++) MMA_FP16(d[mt][nt], ah[mt], bh[nt]);
        }
    }

    // epilogue: acc + bias -> out
#pragma unroll
    for (int mt = 0; mt < 2; mt++) {
#pragma unroll
        for (int nt = 0; nt < 8; nt++) {
            int px = nbase + nt * 8 + 2 * (lane & 3);
            int gp = (ty0 + (px >> 4)) * W + tx0 + (px & 15);
            int co0 = mbase + mt * 16 + (lane >> 2);
            float b0 = s_bias[co0];
            float2 v0; v0.x = d[mt][nt][0] + b0; v0.y = d[mt][nt][1] + b0;
            *(float2*)&out[((size_t)n * C + co0) * HW + gp] = v0;
            int co1 = co0 + 8;
            float b1v = s_bias[co1];
            float2 v1; v1.x = d[mt][nt][2] + b1v; v1.y = d[mt][nt][3] + b1v;
            *(float2*)&out[((size_t)n * C + co1) * HW + gp] = v1;
        }
    }
}

// ---------------------------------------------------------------------------
extern "C" void kernel_launch(void* const* d_in, const int* in_sizes, int n_in,
                              void* d_out, int out_size)
{
    const float* feat  = (const float*)d_in[0];
    const float* wtin  = (const float*)d_in[1];
    const float* w1    = (const float*)d_in[2];
    const float* b1    = (const float*)d_in[3];
    const float* w2    = (const float*)d_in[4];
    const float* b2    = (const float*)d_in[5];
    const float* bb    = (const float*)d_in[6];
    const float* coef  = (const float*)d_in[7];
    const float* bias  = (const float*)d_in[8];
    float* out = (float*)d_out;

    cudaFuncSetAttribute(conv1_mma_kernel,
        cudaFuncAttributeMaxDynamicSharedMemorySize, C1_SMEM);
    cudaFuncSetAttribute(fused_mma_kernel,
        cudaFuncAttributeMaxDynamicSharedMemorySize, F_SMEM);

    w1split_kernel<<<(C * K1 + 255) / 256, 256>>>(w1);
    fpack_kernel<<<(int)(((size_t)NN * CIN * HW + 255) / 256), 256>>>(feat, wtin);
    coefA_kernel<<<C * KPAD / 256, 256>>>(coef);
    conv1_mma_kernel<<<NN * 72, 256, C1_SMEM>>>(b1);
    conv2_bases_kernel<<<dim3(HW / 256, NN), 256>>>(w2, b2, bb);
    fused_mma_kernel<<<NN * 72, 256, F_SMEM>>>(feat, bias, out);
}